// round 1
// baseline (speedup 1.0000x reference)
#include <cuda_runtime.h>
#include <cuda_bf16.h>
#include <math.h>

// Problem constants
#define BB 2
#define TT 2048
#define CC 768
#define HH 12
#define HD 64
#define D2 32
#define FF 3072
#define MROWS (BB*TT)          // 4096
#define EPSV 1e-5f

// ---------------- scratch (device globals; no allocation allowed) ----------
__device__ float g_h [MROWS*CC];
__device__ float g_q [MROWS*CC];
__device__ float g_k [MROWS*CC];
__device__ float g_v [MROWS*CC];
__device__ float g_y [MROWS*CC];
__device__ float g_x2[MROWS*CC];
__device__ float g_a [MROWS*FF];

// ---------------- RMSNorm: one block per row of 768 ------------------------
__global__ void rmsnorm_k(const float* __restrict__ x, const float* __restrict__ g,
                          float* __restrict__ o) {
    int row = blockIdx.x;
    int tid = threadIdx.x;            // 256 threads
    const float* xr = x + (size_t)row * CC;
    float v0 = xr[tid], v1 = xr[tid + 256], v2 = xr[tid + 512];
    float ss = v0*v0 + v1*v1 + v2*v2;
    #pragma unroll
    for (int m = 16; m > 0; m >>= 1) ss += __shfl_xor_sync(0xffffffffu, ss, m);
    __shared__ float ws[8];
    if ((tid & 31) == 0) ws[tid >> 5] = ss;
    __syncthreads();
    float tot = 0.f;
    #pragma unroll
    for (int i = 0; i < 8; i++) tot += ws[i];
    float sc = rsqrtf(tot * (1.0f / CC) + EPSV);
    float* orow = o + (size_t)row * CC;
    orow[tid      ] = g[tid      ] * v0 * sc;
    orow[tid + 256] = g[tid + 256] * v1 * sc;
    orow[tid + 512] = g[tid + 512] * v2 * sc;
}

// ---------------- RoPE in-place on [B,T,H,HD] ------------------------------
__global__ void rope_k(float* __restrict__ q, const float* __restrict__ cs,
                       const float* __restrict__ sn) {
    int idx = blockIdx.x * blockDim.x + threadIdx.x;   // over B*T*H*D2
    if (idx >= BB*TT*HH*D2) return;
    int d = idx & (D2 - 1);
    int h = (idx / D2) % HH;
    int t = (idx / (D2 * HH)) % TT;
    int b = idx / (D2 * HH * TT);
    float* p = q + (((size_t)(b*TT + t))*HH + h) * HD;
    float c = cs[t*D2 + d], s = sn[t*D2 + d];
    float x1 = p[d], x2 = p[d + D2];
    p[d]      =  x1 * c + x2 * s;
    p[d + D2] = -x1 * s + x2 * c;
}

// ---------------- SGEMM 128x128x8, 8x8 per thread --------------------------
// EPI: 0 = plain, 1 = +residual R, 2 = relu(x)^2
template<int EPI>
__global__ void __launch_bounds__(256, 2)
sgemm_k(const float* __restrict__ A, const float* __restrict__ B,
        float* __restrict__ C, const float* __restrict__ R,
        int M, int N, int K) {
    const int BM = 128, BN = 128, BK = 8, TM = 8, TN = 8;
    __shared__ float As[BK * BM];
    __shared__ float Bs[BK * BN];
    int tid = threadIdx.x;
    int crow = blockIdx.y, ccol = blockIdx.x;
    A += (size_t)crow * BM * K;
    B += ccol * BN;
    C += (size_t)crow * BM * N + ccol * BN;
    if (EPI == 1) R += (size_t)crow * BM * N + ccol * BN;
    int innerRowA = tid >> 1, innerColA = tid & 1;     // A: 128 rows x 2 float4
    int innerRowB = tid >> 5, innerColB = tid & 31;    // B: 8 rows x 32 float4
    int threadRow = tid >> 4, threadCol = tid & 15;
    float acc[TM * TN] = {0.f};
    float regM[TM], regN[TN];
    for (int kt = 0; kt < K; kt += BK) {
        float4 a4 = *(const float4*)(A + innerRowA * K + innerColA * 4);
        As[(innerColA*4 + 0) * BM + innerRowA] = a4.x;
        As[(innerColA*4 + 1) * BM + innerRowA] = a4.y;
        As[(innerColA*4 + 2) * BM + innerRowA] = a4.z;
        As[(innerColA*4 + 3) * BM + innerRowA] = a4.w;
        *(float4*)(Bs + innerRowB * BN + innerColB * 4) =
            *(const float4*)(B + innerRowB * N + innerColB * 4);
        __syncthreads();
        A += BK;
        B += (size_t)BK * N;
        #pragma unroll
        for (int k = 0; k < BK; k++) {
            #pragma unroll
            for (int i = 0; i < TM; i++) regM[i] = As[k*BM + threadRow*TM + i];
            #pragma unroll
            for (int j = 0; j < TN; j++) regN[j] = Bs[k*BN + threadCol*TN + j];
            #pragma unroll
            for (int i = 0; i < TM; i++)
                #pragma unroll
                for (int j = 0; j < TN; j++)
                    acc[i*TN + j] += regM[i] * regN[j];
        }
        __syncthreads();
    }
    #pragma unroll
    for (int i = 0; i < TM; i++) {
        int r = threadRow * TM + i;
        #pragma unroll
        for (int j = 0; j < TN; j += 4) {
            int c = threadCol * TN + j;
            float4 v;
            v.x = acc[i*TN+j]; v.y = acc[i*TN+j+1]; v.z = acc[i*TN+j+2]; v.w = acc[i*TN+j+3];
            if (EPI == 1) {
                float4 r4 = *(const float4*)(R + (size_t)r * N + c);
                v.x += r4.x; v.y += r4.y; v.z += r4.z; v.w += r4.w;
            } else if (EPI == 2) {
                v.x = fmaxf(v.x, 0.f); v.x *= v.x;
                v.y = fmaxf(v.y, 0.f); v.y *= v.y;
                v.z = fmaxf(v.z, 0.f); v.z *= v.z;
                v.w = fmaxf(v.w, 0.f); v.w *= v.w;
            }
            *(float4*)(C + (size_t)r * N + c) = v;
        }
    }
}

// ---------------- Flash attention fp32, causal, 64x64 tiles ----------------
// grid: (T/64, B*H); block 256 threads (tx = tid%16 owns 4 HD/key cols,
// ty = tid/16 owns 4 q rows). Qts/Kts stored d-major (transposed) in shared.
// P (post-softmax scores) aliases the Kts buffer.
__global__ void __launch_bounds__(256, 2)
attn_k(const float* __restrict__ Q, const float* __restrict__ K,
       const float* __restrict__ V, float* __restrict__ Y) {
    __shared__ float Qts[64 * 64];   // [d][qrow]
    __shared__ float Kts[64 * 64];   // [d][key]  (later aliased as P[qrow][key])
    __shared__ float Vs [64 * 64];   // [key][d]
    const int qt = blockIdx.x;             // 0..31
    const int bh = blockIdx.y;             // 0..23
    const int b = bh / HH, h = bh % HH;
    const int tid = threadIdx.x;
    const int tx = tid & 15, ty = tid >> 4;
    const size_t base = (((size_t)b * TT) * HH + h) * HD;   // row t -> +t*HH*HD
    const float* Qg = Q + base;
    const float* Kg = K + base;
    const float* Vg = V + base;

    // load Q tile transposed: Qts[d][r]
    for (int i = tid; i < 64 * 16; i += 256) {
        int r = i >> 4, c4 = i & 15;
        float4 qv = *(const float4*)(Qg + (size_t)(qt*64 + r) * (HH*HD) + c4*4);
        Qts[(c4*4 + 0)*64 + r] = qv.x;
        Qts[(c4*4 + 1)*64 + r] = qv.y;
        Qts[(c4*4 + 2)*64 + r] = qv.z;
        Qts[(c4*4 + 3)*64 + r] = qv.w;
    }

    float m[4], l[4], acc_o[16];
    #pragma unroll
    for (int i = 0; i < 4; i++) { m[i] = -1e30f; l[i] = 0.f; }
    #pragma unroll
    for (int i = 0; i < 16; i++) acc_o[i] = 0.f;

    const float scale = 0.125f;   // 1/sqrt(64)

    for (int kt = 0; kt <= qt; kt++) {
        __syncthreads();   // previous iter's P/V reads done
        // load K transposed + V row-major
        for (int i = tid; i < 64 * 16; i += 256) {
            int r = i >> 4, c4 = i & 15;
            float4 kv = *(const float4*)(Kg + (size_t)(kt*64 + r) * (HH*HD) + c4*4);
            Kts[(c4*4 + 0)*64 + r] = kv.x;
            Kts[(c4*4 + 1)*64 + r] = kv.y;
            Kts[(c4*4 + 2)*64 + r] = kv.z;
            Kts[(c4*4 + 3)*64 + r] = kv.w;
            *(float4*)(&Vs[r*64 + c4*4]) =
                *(const float4*)(Vg + (size_t)(kt*64 + r) * (HH*HD) + c4*4);
        }
        __syncthreads();

        // S = Q K^T (4x4 per thread)
        float s[16];
        #pragma unroll
        for (int i = 0; i < 16; i++) s[i] = 0.f;
        #pragma unroll 8
        for (int d = 0; d < 64; d++) {
            float4 qv = *(const float4*)(&Qts[d*64 + ty*4]);
            float4 kv = *(const float4*)(&Kts[d*64 + tx*4]);
            float rq[4] = {qv.x, qv.y, qv.z, qv.w};
            float rk[4] = {kv.x, kv.y, kv.z, kv.w};
            #pragma unroll
            for (int i = 0; i < 4; i++)
                #pragma unroll
                for (int j = 0; j < 4; j++)
                    s[i*4 + j] += rq[i] * rk[j];
        }

        // scale + causal mask
        #pragma unroll
        for (int i = 0; i < 4; i++) {
            int rg = qt*64 + ty*4 + i;
            #pragma unroll
            for (int j = 0; j < 4; j++) {
                int cg = kt*64 + tx*4 + j;
                float v = s[i*4 + j] * scale;
                s[i*4 + j] = (cg <= rg) ? v : -1e30f;
            }
        }

        // online softmax
        float p[16];
        #pragma unroll
        for (int i = 0; i < 4; i++) {
            float rmax = fmaxf(fmaxf(s[i*4], s[i*4+1]), fmaxf(s[i*4+2], s[i*4+3]));
            #pragma unroll
            for (int msk = 1; msk < 16; msk <<= 1)
                rmax = fmaxf(rmax, __shfl_xor_sync(0xffffffffu, rmax, msk));
            float mn = fmaxf(m[i], rmax);
            float f = __expf(m[i] - mn);
            m[i] = mn;
            float rs = 0.f;
            #pragma unroll
            for (int j = 0; j < 4; j++) {
                float pv = __expf(s[i*4 + j] - mn);
                p[i*4 + j] = pv;
                rs += pv;
            }
            #pragma unroll
            for (int msk = 1; msk < 16; msk <<= 1)
                rs += __shfl_xor_sync(0xffffffffu, rs, msk);
            l[i] = l[i] * f + rs;
            #pragma unroll
            for (int j = 0; j < 4; j++) acc_o[i*4 + j] *= f;
        }

        __syncthreads();   // everyone done reading Kts
        // write P into Kts alias: P[qrow][key]
        #pragma unroll
        for (int i = 0; i < 4; i++)
            #pragma unroll
            for (int j = 0; j < 4; j++)
                Kts[(ty*4 + i)*64 + tx*4 + j] = p[i*4 + j];
        __syncthreads();

        // O += P @ V
        #pragma unroll 8
        for (int kk = 0; kk < 64; kk++) {
            float rp[4];
            #pragma unroll
            for (int i = 0; i < 4; i++) rp[i] = Kts[(ty*4 + i)*64 + kk];
            float4 vv = *(const float4*)(&Vs[kk*64 + tx*4]);
            float rv[4] = {vv.x, vv.y, vv.z, vv.w};
            #pragma unroll
            for (int i = 0; i < 4; i++)
                #pragma unroll
                for (int j = 0; j < 4; j++)
                    acc_o[i*4 + j] += rp[i] * rv[j];
        }
    }

    // write Y [B,T,H,HD]
    #pragma unroll
    for (int i = 0; i < 4; i++) {
        float inv = 1.0f / l[i];
        int row = qt*64 + ty*4 + i;
        float4 v;
        v.x = acc_o[i*4+0]*inv; v.y = acc_o[i*4+1]*inv;
        v.z = acc_o[i*4+2]*inv; v.w = acc_o[i*4+3]*inv;
        *(float4*)(Y + base + (size_t)row * (HH*HD) + tx*4) = v;
    }
}

// ---------------- launch ----------------------------------------------------
extern "C" void kernel_launch(void* const* d_in, const int* in_sizes, int n_in,
                              void* d_out, int out_size) {
    const float* x   = (const float*)d_in[0];
    const float* cs  = (const float*)d_in[1];
    const float* sn  = (const float*)d_in[2];
    const float* wq  = (const float*)d_in[3];
    const float* wk  = (const float*)d_in[4];
    const float* wv  = (const float*)d_in[5];
    const float* wo  = (const float*)d_in[6];
    const float* wfc = (const float*)d_in[7];
    const float* wpr = (const float*)d_in[8];
    const float* g1  = (const float*)d_in[9];
    const float* g2  = (const float*)d_in[10];
    float* out = (float*)d_out;

    float *h_, *q_, *k_, *v_, *y_, *x2_, *a_;
    cudaGetSymbolAddress((void**)&h_,  g_h);
    cudaGetSymbolAddress((void**)&q_,  g_q);
    cudaGetSymbolAddress((void**)&k_,  g_k);
    cudaGetSymbolAddress((void**)&v_,  g_v);
    cudaGetSymbolAddress((void**)&y_,  g_y);
    cudaGetSymbolAddress((void**)&x2_, g_x2);
    cudaGetSymbolAddress((void**)&a_,  g_a);

    dim3 gemm_cc(CC/128, MROWS/128);   // (6, 32)
    dim3 gemm_ff(FF/128, MROWS/128);   // (24, 32)

    // 1. h = rmsnorm(x, g1)
    rmsnorm_k<<<MROWS, 256>>>(x, g1, h_);
    // 2. q,k,v = h @ w{q,k,v}
    sgemm_k<0><<<gemm_cc, 256>>>(h_, wq, q_, nullptr, MROWS, CC, CC);
    sgemm_k<0><<<gemm_cc, 256>>>(h_, wk, k_, nullptr, MROWS, CC, CC);
    sgemm_k<0><<<gemm_cc, 256>>>(h_, wv, v_, nullptr, MROWS, CC, CC);
    // 3. RoPE on q, k
    int nrope = BB*TT*HH*D2;
    rope_k<<<(nrope + 255)/256, 256>>>(q_, cs, sn);
    rope_k<<<(nrope + 255)/256, 256>>>(k_, cs, sn);
    // 4. attention -> y [B,T,H,HD]
    attn_k<<<dim3(TT/64, BB*HH), 256>>>(q_, k_, v_, y_);
    // 5. x2 = x + y @ wo
    sgemm_k<1><<<gemm_cc, 256>>>(y_, wo, x2_, x, MROWS, CC, CC);
    // 6. h = rmsnorm(x2, g2)
    rmsnorm_k<<<MROWS, 256>>>(x2_, g2, h_);
    // 7. a = relu(h @ wfc)^2
    sgemm_k<2><<<gemm_ff, 256>>>(h_, wfc, a_, nullptr, MROWS, FF, CC);
    // 8. out = x2 + a @ wpr
    sgemm_k<1><<<gemm_cc, 256>>>(a_, wpr, out, x2_, MROWS, CC, FF);
}

// round 5
// speedup vs baseline: 1.5872x; 1.5872x over previous
#include <cuda_runtime.h>
#include <cuda_bf16.h>
#include <math.h>

// Problem constants
#define BB 2
#define TT 2048
#define CC 768
#define HH 12
#define HD 64
#define D2 32
#define FF 3072
#define MROWS (BB*TT)          // 4096
#define EPSV 1e-5f

// ---------------- scratch ---------------------------------------------------
__device__ float g_h [MROWS*CC];
__device__ float g_q [MROWS*CC];
__device__ float g_k [MROWS*CC];
__device__ float g_v [MROWS*CC];
__device__ float g_y [MROWS*CC];
__device__ float g_x2[MROWS*CC];
__device__ float g_a [MROWS*FF];

// ---------------- helpers ---------------------------------------------------
__device__ __forceinline__ unsigned f2tf(float f) {
    unsigned u;
    asm("cvt.rna.tf32.f32 %0, %1;" : "=r"(u) : "f"(f));
    return u;
}
__device__ __forceinline__ void mma_tf32(float* c, const unsigned* a, const unsigned* b) {
    asm("mma.sync.aligned.m16n8k8.row.col.f32.tf32.tf32.f32 "
        "{%0,%1,%2,%3},{%4,%5,%6,%7},{%8,%9},{%0,%1,%2,%3};"
        : "+f"(c[0]), "+f"(c[1]), "+f"(c[2]), "+f"(c[3])
        : "r"(a[0]), "r"(a[1]), "r"(a[2]), "r"(a[3]), "r"(b[0]), "r"(b[1]));
}

// ---------------- RMSNorm ---------------------------------------------------
__global__ void rmsnorm_k(const float* __restrict__ x, const float* __restrict__ g,
                          float* __restrict__ o) {
    int row = blockIdx.x;
    int tid = threadIdx.x;            // 256 threads
    const float* xr = x + (size_t)row * CC;
    float v0 = xr[tid], v1 = xr[tid + 256], v2 = xr[tid + 512];
    float ss = v0*v0 + v1*v1 + v2*v2;
    #pragma unroll
    for (int m = 16; m > 0; m >>= 1) ss += __shfl_xor_sync(0xffffffffu, ss, m);
    __shared__ float ws[8];
    if ((tid & 31) == 0) ws[tid >> 5] = ss;
    __syncthreads();
    float tot = 0.f;
    #pragma unroll
    for (int i = 0; i < 8; i++) tot += ws[i];
    float sc = rsqrtf(tot * (1.0f / CC) + EPSV);
    float* orow = o + (size_t)row * CC;
    orow[tid      ] = g[tid      ] * v0 * sc;
    orow[tid + 256] = g[tid + 256] * v1 * sc;
    orow[tid + 512] = g[tid + 512] * v2 * sc;
}

// ---------------- RoPE in-place on [B,T,H,HD] ------------------------------
__global__ void rope_k(float* __restrict__ q, const float* __restrict__ cs,
                       const float* __restrict__ sn) {
    int idx = blockIdx.x * blockDim.x + threadIdx.x;   // over B*T*H*D2
    if (idx >= BB*TT*HH*D2) return;
    int d = idx & (D2 - 1);
    int h = (idx / D2) % HH;
    int t = (idx / (D2 * HH)) % TT;
    int b = idx / (D2 * HH * TT);
    float* p = q + (((size_t)(b*TT + t))*HH + h) * HD;
    float c = cs[t*D2 + d], s = sn[t*D2 + d];
    float x1 = p[d], x2 = p[d + D2];
    p[d]      =  x1 * c + x2 * s;
    p[d + D2] = -x1 * s + x2 * c;
}

// ---------------- TF32 tensor-core GEMM 128x128x32 --------------------------
// 256 threads = 8 warps in 2(M) x 4(N); warp tile 64x32; mma.m16n8k8.
// Shared memory holds fragment-packed tiles:
//   A: 32 tiles (mt 0..7, kt 0..3), each 32 lanes x {a0,a1,a2,a3} -> LDS.128
//   B: 64 tiles (nt 0..15, kt 0..3), each 32 lanes x {b0,b1}      -> LDS.64
// EPI: 0 = plain, 1 = +residual R, 2 = relu(x)^2
template<int EPI>
__global__ void __launch_bounds__(256)
tfgemm_k(const float* __restrict__ A, const float* __restrict__ B,
         float* __restrict__ C, const float* __restrict__ R,
         int M, int N, int K) {
    __shared__ unsigned As[4096];     // 8 mt * 4 kt * 128
    __shared__ unsigned Bs[4096];     // 16 nt * 4 kt * 64
    const int tid  = threadIdx.x;
    const int warp = tid >> 5, lane = tid & 31;
    const int wm = warp >> 2, wn = warp & 3;
    const int bm = blockIdx.y * 128, bn = blockIdx.x * 128;
    const float* Ab = A + (size_t)bm * K;
    const float* Bb = B + bn;

    float acc[4][4][4];
    #pragma unroll
    for (int i = 0; i < 4; i++)
        #pragma unroll
        for (int j = 0; j < 4; j++)
            #pragma unroll
            for (int t = 0; t < 4; t++) acc[i][j][t] = 0.f;

    float4 areg[4], breg[4];
    const int NB = K >> 5;

    // per-thread load/store coords (constant across stages)
    // A: idx = it*256+tid -> m = idx>>3 (0..127), k4 = idx&7 (float4 within 32)
    // B: kr = idx>>5 (0..31), n4 = idx&31

    #define LDG_STAGE(kb)                                                        \
        _Pragma("unroll")                                                        \
        for (int it = 0; it < 4; it++) {                                         \
            int idx = it*256 + tid;                                              \
            int m = idx >> 3, k4 = idx & 7;                                      \
            areg[it] = *(const float4*)(Ab + (size_t)m*K + (kb)*32 + k4*4);      \
            int kr = idx >> 5, n4 = idx & 31;                                    \
            breg[it] = *(const float4*)(Bb + (size_t)((kb)*32 + kr)*N + n4*4);   \
        }

    #define STS_STAGE()                                                          \
        _Pragma("unroll")                                                        \
        for (int it = 0; it < 4; it++) {                                         \
            int idx = it*256 + tid;                                              \
            int m = idx >> 3, k4 = idx & 7;                                      \
            int mt = m >> 4, row = m & 15;                                       \
            int kt = k4 >> 1;                                                    \
            int slot = ((row & 8) ? 1 : 0) + ((k4 & 1) ? 2 : 0);                 \
            int ln0 = (row & 7) * 4;                                             \
            unsigned* ab = &As[(kt*8 + mt)*128 + slot];                          \
            const float* av = (const float*)&areg[it];                           \
            _Pragma("unroll")                                                    \
            for (int j = 0; j < 4; j++) ab[(ln0 + j)*4] = f2tf(av[j]);           \
            int kr = idx >> 5, n4 = idx & 31;                                    \
            int kt2 = kr >> 3, kr8 = kr & 7;                                     \
            int bslot = (kr8 >= 4) ? 1 : 0, kin = kr8 & 3;                       \
            int nt = n4 >> 1;                                                    \
            unsigned* bb = &Bs[(kt2*16 + nt)*64 + bslot];                        \
            const float* bv = (const float*)&breg[it];                           \
            _Pragma("unroll")                                                    \
            for (int j = 0; j < 4; j++) {                                        \
                int ln = ((n4 & 1)*4 + j)*4 + kin;                               \
                bb[ln*2] = f2tf(bv[j]);                                          \
            }                                                                    \
        }

    LDG_STAGE(0)
    STS_STAGE()
    __syncthreads();

    for (int kb = 0; kb < NB; kb++) {
        if (kb + 1 < NB) { LDG_STAGE(kb + 1) }
        #pragma unroll
        for (int kt = 0; kt < 4; kt++) {
            unsigned a[4][4], b[4][2];
            #pragma unroll
            for (int i = 0; i < 4; i++) {
                int mt = wm*4 + i;
                *(uint4*)a[i] = *(const uint4*)&As[(kt*8 + mt)*128 + lane*4];
            }
            #pragma unroll
            for (int j = 0; j < 4; j++) {
                int nt = wn*4 + j;
                uint2 bv = *(const uint2*)&Bs[(kt*16 + nt)*64 + lane*2];
                b[j][0] = bv.x; b[j][1] = bv.y;
            }
            #pragma unroll
            for (int i = 0; i < 4; i++)
                #pragma unroll
                for (int j = 0; j < 4; j++)
                    mma_tf32(acc[i][j], a[i], b[j]);
        }
        __syncthreads();
        if (kb + 1 < NB) { STS_STAGE() }
        __syncthreads();
    }

    // epilogue
    #pragma unroll
    for (int i = 0; i < 4; i++) {
        int r = bm + (wm*4 + i)*16 + (lane >> 2);
        #pragma unroll
        for (int j = 0; j < 4; j++) {
            int c = bn + (wn*4 + j)*8 + (lane & 3)*2;
            float2 v0 = make_float2(acc[i][j][0], acc[i][j][1]);
            float2 v1 = make_float2(acc[i][j][2], acc[i][j][3]);
            if (EPI == 1) {
                float2 r0 = *(const float2*)(R + (size_t)r*N + c);
                float2 r1 = *(const float2*)(R + (size_t)(r+8)*N + c);
                v0.x += r0.x; v0.y += r0.y;
                v1.x += r1.x; v1.y += r1.y;
            } else if (EPI == 2) {
                v0.x = fmaxf(v0.x, 0.f); v0.x *= v0.x;
                v0.y = fmaxf(v0.y, 0.f); v0.y *= v0.y;
                v1.x = fmaxf(v1.x, 0.f); v1.x *= v1.x;
                v1.y = fmaxf(v1.y, 0.f); v1.y *= v1.y;
            }
            *(float2*)(C + (size_t)r*N + c)     = v0;
            *(float2*)(C + (size_t)(r+8)*N + c) = v1;
        }
    }
    #undef LDG_STAGE
    #undef STS_STAGE
}

// ---------------- Flash attention fp32, causal, 64x64 tiles ----------------
__global__ void __launch_bounds__(256, 2)
attn_k(const float* __restrict__ Q, const float* __restrict__ K,
       const float* __restrict__ V, float* __restrict__ Y) {
    __shared__ float Qts[64 * 64];   // [d][qrow]
    __shared__ float Kts[64 * 64];   // [d][key]  (aliased as P[qrow][key])
    __shared__ float Vs [64 * 64];   // [key][d]
    const int qt = blockIdx.x;
    const int bh = blockIdx.y;
    const int b = bh / HH, h = bh % HH;
    const int tid = threadIdx.x;
    const int tx = tid & 15, ty = tid >> 4;
    const size_t base = (((size_t)b * TT) * HH + h) * HD;
    const float* Qg = Q + base;
    const float* Kg = K + base;
    const float* Vg = V + base;

    for (int i = tid; i < 64 * 16; i += 256) {
        int r = i >> 4, c4 = i & 15;
        float4 qv = *(const float4*)(Qg + (size_t)(qt*64 + r) * (HH*HD) + c4*4);
        Qts[(c4*4 + 0)*64 + r] = qv.x;
        Qts[(c4*4 + 1)*64 + r] = qv.y;
        Qts[(c4*4 + 2)*64 + r] = qv.z;
        Qts[(c4*4 + 3)*64 + r] = qv.w;
    }

    float m[4], l[4], acc_o[16];
    #pragma unroll
    for (int i = 0; i < 4; i++) { m[i] = -1e30f; l[i] = 0.f; }
    #pragma unroll
    for (int i = 0; i < 16; i++) acc_o[i] = 0.f;

    const float scale = 0.125f;

    for (int kt = 0; kt <= qt; kt++) {
        __syncthreads();
        for (int i = tid; i < 64 * 16; i += 256) {
            int r = i >> 4, c4 = i & 15;
            float4 kv = *(const float4*)(Kg + (size_t)(kt*64 + r) * (HH*HD) + c4*4);
            Kts[(c4*4 + 0)*64 + r] = kv.x;
            Kts[(c4*4 + 1)*64 + r] = kv.y;
            Kts[(c4*4 + 2)*64 + r] = kv.z;
            Kts[(c4*4 + 3)*64 + r] = kv.w;
            *(float4*)(&Vs[r*64 + c4*4]) =
                *(const float4*)(Vg + (size_t)(kt*64 + r) * (HH*HD) + c4*4);
        }
        __syncthreads();

        float s[16];
        #pragma unroll
        for (int i = 0; i < 16; i++) s[i] = 0.f;
        #pragma unroll 8
        for (int d = 0; d < 64; d++) {
            float4 qv = *(const float4*)(&Qts[d*64 + ty*4]);
            float4 kv = *(const float4*)(&Kts[d*64 + tx*4]);
            float rq[4] = {qv.x, qv.y, qv.z, qv.w};
            float rk[4] = {kv.x, kv.y, kv.z, kv.w};
            #pragma unroll
            for (int i = 0; i < 4; i++)
                #pragma unroll
                for (int j = 0; j < 4; j++)
                    s[i*4 + j] += rq[i] * rk[j];
        }

        #pragma unroll
        for (int i = 0; i < 4; i++) {
            int rg = qt*64 + ty*4 + i;
            #pragma unroll
            for (int j = 0; j < 4; j++) {
                int cg = kt*64 + tx*4 + j;
                float v = s[i*4 + j] * scale;
                s[i*4 + j] = (cg <= rg) ? v : -1e30f;
            }
        }

        float p[16];
        #pragma unroll
        for (int i = 0; i < 4; i++) {
            float rmax = fmaxf(fmaxf(s[i*4], s[i*4+1]), fmaxf(s[i*4+2], s[i*4+3]));
            #pragma unroll
            for (int msk = 1; msk < 16; msk <<= 1)
                rmax = fmaxf(rmax, __shfl_xor_sync(0xffffffffu, rmax, msk));
            float mn = fmaxf(m[i], rmax);
            float f = __expf(m[i] - mn);
            m[i] = mn;
            float rs = 0.f;
            #pragma unroll
            for (int j = 0; j < 4; j++) {
                float pv = __expf(s[i*4 + j] - mn);
                p[i*4 + j] = pv;
                rs += pv;
            }
            #pragma unroll
            for (int msk = 1; msk < 16; msk <<= 1)
                rs += __shfl_xor_sync(0xffffffffu, rs, msk);
            l[i] = l[i] * f + rs;
            #pragma unroll
            for (int j = 0; j < 4; j++) acc_o[i*4 + j] *= f;
        }

        __syncthreads();
        #pragma unroll
        for (int i = 0; i < 4; i++)
            #pragma unroll
            for (int j = 0; j < 4; j++)
                Kts[(ty*4 + i)*64 + tx*4 + j] = p[i*4 + j];
        __syncthreads();

        #pragma unroll 8
        for (int kk = 0; kk < 64; kk++) {
            float rp[4];
            #pragma unroll
            for (int i = 0; i < 4; i++) rp[i] = Kts[(ty*4 + i)*64 + kk];
            float4 vv = *(const float4*)(&Vs[kk*64 + tx*4]);
            float rv[4] = {vv.x, vv.y, vv.z, vv.w};
            #pragma unroll
            for (int i = 0; i < 4; i++)
                #pragma unroll
                for (int j = 0; j < 4; j++)
                    acc_o[i*4 + j] += rp[i] * rv[j];
        }
    }

    #pragma unroll
    for (int i = 0; i < 4; i++) {
        float inv = 1.0f / l[i];
        int row = qt*64 + ty*4 + i;
        float4 v;
        v.x = acc_o[i*4+0]*inv; v.y = acc_o[i*4+1]*inv;
        v.z = acc_o[i*4+2]*inv; v.w = acc_o[i*4+3]*inv;
        *(float4*)(Y + base + (size_t)row * (HH*HD) + tx*4) = v;
    }
}

// ---------------- launch ----------------------------------------------------
extern "C" void kernel_launch(void* const* d_in, const int* in_sizes, int n_in,
                              void* d_out, int out_size) {
    const float* x   = (const float*)d_in[0];
    const float* cs  = (const float*)d_in[1];
    const float* sn  = (const float*)d_in[2];
    const float* wq  = (const float*)d_in[3];
    const float* wk  = (const float*)d_in[4];
    const float* wv  = (const float*)d_in[5];
    const float* wo  = (const float*)d_in[6];
    const float* wfc = (const float*)d_in[7];
    const float* wpr = (const float*)d_in[8];
    const float* g1  = (const float*)d_in[9];
    const float* g2  = (const float*)d_in[10];
    float* out = (float*)d_out;

    float *h_, *q_, *k_, *v_, *y_, *x2_, *a_;
    cudaGetSymbolAddress((void**)&h_,  g_h);
    cudaGetSymbolAddress((void**)&q_,  g_q);
    cudaGetSymbolAddress((void**)&k_,  g_k);
    cudaGetSymbolAddress((void**)&v_,  g_v);
    cudaGetSymbolAddress((void**)&y_,  g_y);
    cudaGetSymbolAddress((void**)&x2_, g_x2);
    cudaGetSymbolAddress((void**)&a_,  g_a);

    dim3 gemm_cc(CC/128, MROWS/128);   // (6, 32)
    dim3 gemm_ff(FF/128, MROWS/128);   // (24, 32)

    // 1. h = rmsnorm(x, g1)
    rmsnorm_k<<<MROWS, 256>>>(x, g1, h_);
    // 2. q,k,v = h @ w{q,k,v}
    tfgemm_k<0><<<gemm_cc, 256>>>(h_, wq, q_, nullptr, MROWS, CC, CC);
    tfgemm_k<0><<<gemm_cc, 256>>>(h_, wk, k_, nullptr, MROWS, CC, CC);
    tfgemm_k<0><<<gemm_cc, 256>>>(h_, wv, v_, nullptr, MROWS, CC, CC);
    // 3. RoPE on q, k
    int nrope = BB*TT*HH*D2;
    rope_k<<<(nrope + 255)/256, 256>>>(q_, cs, sn);
    rope_k<<<(nrope + 255)/256, 256>>>(k_, cs, sn);
    // 4. attention -> y [B,T,H,HD]
    attn_k<<<dim3(TT/64, BB*HH), 256>>>(q_, k_, v_, y_);
    // 5. x2 = x + y @ wo
    tfgemm_k<1><<<gemm_cc, 256>>>(y_, wo, x2_, x, MROWS, CC, CC);
    // 6. h = rmsnorm(x2, g2)
    rmsnorm_k<<<MROWS, 256>>>(x2_, g2, h_);
    // 7. a = relu(h @ wfc)^2
    tfgemm_k<2><<<gemm_ff, 256>>>(h_, wfc, a_, nullptr, MROWS, FF, CC);
    // 8. out = x2 + a @ wpr
    tfgemm_k<1><<<gemm_cc, 256>>>(a_, wpr, out, x2_, MROWS, CC, FF);
}

// round 6
// speedup vs baseline: 1.7954x; 1.1312x over previous
#include <cuda_runtime.h>
#include <cuda_bf16.h>
#include <math.h>

// Problem constants
#define BB 2
#define TT 2048
#define CC 768
#define HH 12
#define HD 64
#define D2 32
#define FF 3072
#define MROWS (BB*TT)          // 4096
#define EPSV 1e-5f

// ---------------- scratch ---------------------------------------------------
__device__ float g_h [MROWS*CC];
__device__ float g_q [MROWS*CC];
__device__ float g_k [MROWS*CC];
__device__ float g_v [MROWS*CC];
__device__ float g_y [MROWS*CC];
__device__ float g_x2[MROWS*CC];
__device__ float g_a [MROWS*FF];

// ---------------- helpers ---------------------------------------------------
__device__ __forceinline__ unsigned f2tf(float f) {
    unsigned u;
    asm("cvt.rna.tf32.f32 %0, %1;" : "=r"(u) : "f"(f));
    return u;
}
__device__ __forceinline__ void mma_tf32(float* c, const unsigned* a, const unsigned* b) {
    asm("mma.sync.aligned.m16n8k8.row.col.f32.tf32.tf32.f32 "
        "{%0,%1,%2,%3},{%4,%5,%6,%7},{%8,%9},{%0,%1,%2,%3};"
        : "+f"(c[0]), "+f"(c[1]), "+f"(c[2]), "+f"(c[3])
        : "r"(a[0]), "r"(a[1]), "r"(a[2]), "r"(a[3]), "r"(b[0]), "r"(b[1]));
}

// ---------------- RMSNorm ---------------------------------------------------
__global__ void rmsnorm_k(const float* __restrict__ x, const float* __restrict__ g,
                          float* __restrict__ o) {
    int row = blockIdx.x;
    int tid = threadIdx.x;            // 256 threads
    const float* xr = x + (size_t)row * CC;
    float v0 = xr[tid], v1 = xr[tid + 256], v2 = xr[tid + 512];
    float ss = v0*v0 + v1*v1 + v2*v2;
    #pragma unroll
    for (int m = 16; m > 0; m >>= 1) ss += __shfl_xor_sync(0xffffffffu, ss, m);
    __shared__ float ws[8];
    if ((tid & 31) == 0) ws[tid >> 5] = ss;
    __syncthreads();
    float tot = 0.f;
    #pragma unroll
    for (int i = 0; i < 8; i++) tot += ws[i];
    float sc = rsqrtf(tot * (1.0f / CC) + EPSV);
    float* orow = o + (size_t)row * CC;
    orow[tid      ] = g[tid      ] * v0 * sc;
    orow[tid + 256] = g[tid + 256] * v1 * sc;
    orow[tid + 512] = g[tid + 512] * v2 * sc;
}

// ---------------- RoPE in-place, q and k in one launch (z) ------------------
__global__ void rope_k(float* __restrict__ q, float* __restrict__ k,
                       const float* __restrict__ cs, const float* __restrict__ sn) {
    int idx = blockIdx.x * blockDim.x + threadIdx.x;   // over B*T*H*D2
    if (idx >= BB*TT*HH*D2) return;
    float* base = (blockIdx.y == 0) ? q : k;
    int d = idx & (D2 - 1);
    int h = (idx / D2) % HH;
    int t = (idx / (D2 * HH)) % TT;
    int b = idx / (D2 * HH * TT);
    float* p = base + (((size_t)(b*TT + t))*HH + h) * HD;
    float c = cs[t*D2 + d], s = sn[t*D2 + d];
    float x1 = p[d], x2 = p[d + D2];
    p[d]      =  x1 * c + x2 * s;
    p[d + D2] = -x1 * s + x2 * c;
}

// ---------------- TF32 tensor-core GEMM 128x128x16, pipelined ---------------
// 256 threads = 8 warps in 2(M) x 4(N); warp tile 64x32; mma.m16n8k8.
// 2-stage smem double buffer + 2-set register staging:
//   iter kb: STS regs(kb+1) [loaded last iter -> no scoreboard wait],
//            LDG(kb+2), MMA(buf kb&1), ONE __syncthreads.
// Fragment-packed smem (validated layout): A-frag LDS.128, B-frag LDS.64.
// blockIdx.z selects among (B0,C0)/(B1,C1)/(B2,C2) for fused QKV.
// EPI: 0 = plain, 1 = +residual R, 2 = relu(x)^2
template<int EPI>
__global__ void __launch_bounds__(256)
tfgemm_k(const float* __restrict__ A,
         const float* __restrict__ B0, const float* __restrict__ B1,
         const float* __restrict__ B2,
         float* __restrict__ C0, float* __restrict__ C1, float* __restrict__ C2,
         const float* __restrict__ R, int M, int N, int K) {
    __shared__ unsigned As[2][2048];   // per stage: 16 tiles (kt0..1, mt0..7) * 128
    __shared__ unsigned Bs[2][2048];   // per stage: 32 tiles (kt0..1, nt0..15) * 64
    const int tid  = threadIdx.x;
    const int warp = tid >> 5, lane = tid & 31;
    const int wm = warp >> 2, wn = warp & 3;
    const int bm = blockIdx.y * 128, bn = blockIdx.x * 128;
    const float* Bsel = (blockIdx.z == 0) ? B0 : ((blockIdx.z == 1) ? B1 : B2);
    float*       Csel = (blockIdx.z == 0) ? C0 : ((blockIdx.z == 1) ? C1 : C2);
    const float* Ab = A + (size_t)bm * K;
    const float* Bb = Bsel + bn;

    float acc[4][4][4];
    #pragma unroll
    for (int i = 0; i < 4; i++)
        #pragma unroll
        for (int j = 0; j < 4; j++)
            #pragma unroll
            for (int t = 0; t < 4; t++) acc[i][j][t] = 0.f;

    float4 r0a[2], r0b[2], r1a[2], r1b[2];
    const int NB = K >> 4;             // K multiple of 32 -> NB even, >= 2

    // A: idx = it*256+tid -> m = idx>>2 (0..127), k4 = idx&3 (float4 within 16)
    // B: kr = idx>>5 (0..15), n4 = idx&31
    #define LDG_STAGE(kb, ra, rb)                                                \
        _Pragma("unroll")                                                        \
        for (int it = 0; it < 2; it++) {                                         \
            int idx = it*256 + tid;                                              \
            int m = idx >> 2, k4 = idx & 3;                                      \
            ra[it] = *(const float4*)(Ab + (size_t)m*K + (kb)*16 + k4*4);        \
            int kr = idx >> 5, n4 = idx & 31;                                    \
            rb[it] = *(const float4*)(Bb + (size_t)((kb)*16 + kr)*N + n4*4);     \
        }

    #define STS_STAGE(buf, ra, rb)                                               \
        _Pragma("unroll")                                                        \
        for (int it = 0; it < 2; it++) {                                         \
            int idx = it*256 + tid;                                              \
            int m = idx >> 2, k4 = idx & 3;                                      \
            int mt = m >> 4, row = m & 15;                                       \
            int kt = k4 >> 1;                                                    \
            int slot = ((row & 8) ? 1 : 0) + ((k4 & 1) ? 2 : 0);                 \
            int ln0 = (row & 7) * 4;                                             \
            unsigned* ab = &As[buf][(kt*8 + mt)*128 + slot];                     \
            const float* av = (const float*)&ra[it];                             \
            _Pragma("unroll")                                                    \
            for (int j = 0; j < 4; j++) ab[(ln0 + j)*4] = f2tf(av[j]);           \
            int kr = idx >> 5, n4 = idx & 31;                                    \
            int kt2 = kr >> 3, kr8 = kr & 7;                                     \
            int bslot = (kr8 >= 4) ? 1 : 0, kin = kr8 & 3;                       \
            int nt = n4 >> 1;                                                    \
            unsigned* bb = &Bs[buf][(kt2*16 + nt)*64 + bslot];                   \
            const float* bv = (const float*)&rb[it];                             \
            _Pragma("unroll")                                                    \
            for (int j = 0; j < 4; j++) {                                        \
                int ln = ((n4 & 1)*4 + j)*4 + kin;                               \
                bb[ln*2] = f2tf(bv[j]);                                          \
            }                                                                    \
        }

    #define MMA_STAGE(buf)                                                       \
        _Pragma("unroll")                                                        \
        for (int kt = 0; kt < 2; kt++) {                                         \
            unsigned a[4][4], b[4][2];                                           \
            _Pragma("unroll")                                                    \
            for (int i = 0; i < 4; i++)                                          \
                *(uint4*)a[i] =                                                  \
                    *(const uint4*)&As[buf][(kt*8 + wm*4 + i)*128 + lane*4];     \
            _Pragma("unroll")                                                    \
            for (int j = 0; j < 4; j++) {                                        \
                uint2 bv =                                                       \
                    *(const uint2*)&Bs[buf][(kt*16 + wn*4 + j)*64 + lane*2];     \
                b[j][0] = bv.x; b[j][1] = bv.y;                                  \
            }                                                                    \
            _Pragma("unroll")                                                    \
            for (int i = 0; i < 4; i++)                                          \
                _Pragma("unroll")                                                \
                for (int j = 0; j < 4; j++)                                      \
                    mma_tf32(acc[i][j], a[i], b[j]);                             \
        }

    // prologue: block0 -> set0/buf0, block1 -> set1
    LDG_STAGE(0, r0a, r0b)
    STS_STAGE(0, r0a, r0b)
    LDG_STAGE(1, r1a, r1b)
    __syncthreads();

    for (int kb = 0; kb < NB; kb += 2) {
        // even iter: consume buf0; stage block kb+1 (set1) into buf1; load kb+2 into set0
        STS_STAGE(1, r1a, r1b)
        if (kb + 2 < NB) { LDG_STAGE(kb + 2, r0a, r0b) }
        MMA_STAGE(0)
        __syncthreads();
        // odd iter: consume buf1; stage block kb+2 (set0) into buf0; load kb+3 into set1
        if (kb + 2 < NB) {
            STS_STAGE(0, r0a, r0b)
            if (kb + 3 < NB) { LDG_STAGE(kb + 3, r1a, r1b) }
        }
        MMA_STAGE(1)
        __syncthreads();
    }

    // epilogue
    #pragma unroll
    for (int i = 0; i < 4; i++) {
        int r = bm + (wm*4 + i)*16 + (lane >> 2);
        #pragma unroll
        for (int j = 0; j < 4; j++) {
            int c = bn + (wn*4 + j)*8 + (lane & 3)*2;
            float2 v0 = make_float2(acc[i][j][0], acc[i][j][1]);
            float2 v1 = make_float2(acc[i][j][2], acc[i][j][3]);
            if (EPI == 1) {
                float2 rr0 = *(const float2*)(R + (size_t)r*N + c);
                float2 rr1 = *(const float2*)(R + (size_t)(r+8)*N + c);
                v0.x += rr0.x; v0.y += rr0.y;
                v1.x += rr1.x; v1.y += rr1.y;
            } else if (EPI == 2) {
                v0.x = fmaxf(v0.x, 0.f); v0.x *= v0.x;
                v0.y = fmaxf(v0.y, 0.f); v0.y *= v0.y;
                v1.x = fmaxf(v1.x, 0.f); v1.x *= v1.x;
                v1.y = fmaxf(v1.y, 0.f); v1.y *= v1.y;
            }
            *(float2*)(Csel + (size_t)r*N + c)     = v0;
            *(float2*)(Csel + (size_t)(r+8)*N + c) = v1;
        }
    }
    #undef LDG_STAGE
    #undef STS_STAGE
    #undef MMA_STAGE
}

// ---------------- Flash attention fp32, causal, 64x64 tiles ----------------
__global__ void __launch_bounds__(256, 2)
attn_k(const float* __restrict__ Q, const float* __restrict__ K,
       const float* __restrict__ V, float* __restrict__ Y) {
    __shared__ float Qts[64 * 64];   // [d][qrow]
    __shared__ float Kts[64 * 64];   // [d][key]  (aliased as P[qrow][key])
    __shared__ float Vs [64 * 64];   // [key][d]
    const int qt = blockIdx.x;
    const int bh = blockIdx.y;
    const int b = bh / HH, h = bh % HH;
    const int tid = threadIdx.x;
    const int tx = tid & 15, ty = tid >> 4;
    const size_t base = (((size_t)b * TT) * HH + h) * HD;
    const float* Qg = Q + base;
    const float* Kg = K + base;
    const float* Vg = V + base;

    for (int i = tid; i < 64 * 16; i += 256) {
        int r = i >> 4, c4 = i & 15;
        float4 qv = *(const float4*)(Qg + (size_t)(qt*64 + r) * (HH*HD) + c4*4);
        Qts[(c4*4 + 0)*64 + r] = qv.x;
        Qts[(c4*4 + 1)*64 + r] = qv.y;
        Qts[(c4*4 + 2)*64 + r] = qv.z;
        Qts[(c4*4 + 3)*64 + r] = qv.w;
    }

    float m[4], l[4], acc_o[16];
    #pragma unroll
    for (int i = 0; i < 4; i++) { m[i] = -1e30f; l[i] = 0.f; }
    #pragma unroll
    for (int i = 0; i < 16; i++) acc_o[i] = 0.f;

    const float scale = 0.125f;

    for (int kt = 0; kt <= qt; kt++) {
        __syncthreads();
        for (int i = tid; i < 64 * 16; i += 256) {
            int r = i >> 4, c4 = i & 15;
            float4 kv = *(const float4*)(Kg + (size_t)(kt*64 + r) * (HH*HD) + c4*4);
            Kts[(c4*4 + 0)*64 + r] = kv.x;
            Kts[(c4*4 + 1)*64 + r] = kv.y;
            Kts[(c4*4 + 2)*64 + r] = kv.z;
            Kts[(c4*4 + 3)*64 + r] = kv.w;
            *(float4*)(&Vs[r*64 + c4*4]) =
                *(const float4*)(Vg + (size_t)(kt*64 + r) * (HH*HD) + c4*4);
        }
        __syncthreads();

        float s[16];
        #pragma unroll
        for (int i = 0; i < 16; i++) s[i] = 0.f;
        #pragma unroll 8
        for (int d = 0; d < 64; d++) {
            float4 qv = *(const float4*)(&Qts[d*64 + ty*4]);
            float4 kv = *(const float4*)(&Kts[d*64 + tx*4]);
            float rq[4] = {qv.x, qv.y, qv.z, qv.w};
            float rk[4] = {kv.x, kv.y, kv.z, kv.w};
            #pragma unroll
            for (int i = 0; i < 4; i++)
                #pragma unroll
                for (int j = 0; j < 4; j++)
                    s[i*4 + j] += rq[i] * rk[j];
        }

        #pragma unroll
        for (int i = 0; i < 4; i++) {
            int rg = qt*64 + ty*4 + i;
            #pragma unroll
            for (int j = 0; j < 4; j++) {
                int cg = kt*64 + tx*4 + j;
                float v = s[i*4 + j] * scale;
                s[i*4 + j] = (cg <= rg) ? v : -1e30f;
            }
        }

        float p[16];
        #pragma unroll
        for (int i = 0; i < 4; i++) {
            float rmax = fmaxf(fmaxf(s[i*4], s[i*4+1]), fmaxf(s[i*4+2], s[i*4+3]));
            #pragma unroll
            for (int msk = 1; msk < 16; msk <<= 1)
                rmax = fmaxf(rmax, __shfl_xor_sync(0xffffffffu, rmax, msk));
            float mn = fmaxf(m[i], rmax);
            float f = __expf(m[i] - mn);
            m[i] = mn;
            float rs = 0.f;
            #pragma unroll
            for (int j = 0; j < 4; j++) {
                float pv = __expf(s[i*4 + j] - mn);
                p[i*4 + j] = pv;
                rs += pv;
            }
            #pragma unroll
            for (int msk = 1; msk < 16; msk <<= 1)
                rs += __shfl_xor_sync(0xffffffffu, rs, msk);
            l[i] = l[i] * f + rs;
            #pragma unroll
            for (int j = 0; j < 4; j++) acc_o[i*4 + j] *= f;
        }

        __syncthreads();
        #pragma unroll
        for (int i = 0; i < 4; i++)
            #pragma unroll
            for (int j = 0; j < 4; j++)
                Kts[(ty*4 + i)*64 + tx*4 + j] = p[i*4 + j];
        __syncthreads();

        #pragma unroll 8
        for (int kk = 0; kk < 64; kk++) {
            float rp[4];
            #pragma unroll
            for (int i = 0; i < 4; i++) rp[i] = Kts[(ty*4 + i)*64 + kk];
            float4 vv = *(const float4*)(&Vs[kk*64 + tx*4]);
            float rv[4] = {vv.x, vv.y, vv.z, vv.w};
            #pragma unroll
            for (int i = 0; i < 4; i++)
                #pragma unroll
                for (int j = 0; j < 4; j++)
                    acc_o[i*4 + j] += rp[i] * rv[j];
        }
    }

    #pragma unroll
    for (int i = 0; i < 4; i++) {
        float inv = 1.0f / l[i];
        int row = qt*64 + ty*4 + i;
        float4 v;
        v.x = acc_o[i*4+0]*inv; v.y = acc_o[i*4+1]*inv;
        v.z = acc_o[i*4+2]*inv; v.w = acc_o[i*4+3]*inv;
        *(float4*)(Y + base + (size_t)row * (HH*HD) + tx*4) = v;
    }
}

// ---------------- launch ----------------------------------------------------
extern "C" void kernel_launch(void* const* d_in, const int* in_sizes, int n_in,
                              void* d_out, int out_size) {
    const float* x   = (const float*)d_in[0];
    const float* cs  = (const float*)d_in[1];
    const float* sn  = (const float*)d_in[2];
    const float* wq  = (const float*)d_in[3];
    const float* wk  = (const float*)d_in[4];
    const float* wv  = (const float*)d_in[5];
    const float* wo  = (const float*)d_in[6];
    const float* wfc = (const float*)d_in[7];
    const float* wpr = (const float*)d_in[8];
    const float* g1  = (const float*)d_in[9];
    const float* g2  = (const float*)d_in[10];
    float* out = (float*)d_out;

    float *h_, *q_, *k_, *v_, *y_, *x2_, *a_;
    cudaGetSymbolAddress((void**)&h_,  g_h);
    cudaGetSymbolAddress((void**)&q_,  g_q);
    cudaGetSymbolAddress((void**)&k_,  g_k);
    cudaGetSymbolAddress((void**)&v_,  g_v);
    cudaGetSymbolAddress((void**)&y_,  g_y);
    cudaGetSymbolAddress((void**)&x2_, g_x2);
    cudaGetSymbolAddress((void**)&a_,  g_a);

    dim3 gemm_qkv(CC/128, MROWS/128, 3);  // (6, 32, 3) fused QKV
    dim3 gemm_cc (CC/128, MROWS/128, 1);  // (6, 32)
    dim3 gemm_ff (FF/128, MROWS/128, 1);  // (24, 32)

    // 1. h = rmsnorm(x, g1)
    rmsnorm_k<<<MROWS, 256>>>(x, g1, h_);
    // 2. q,k,v = h @ w{q,k,v}  (one fused launch)
    tfgemm_k<0><<<gemm_qkv, 256>>>(h_, wq, wk, wv, q_, k_, v_, nullptr, MROWS, CC, CC);
    // 3. RoPE on q and k (one launch)
    int nrope = BB*TT*HH*D2;
    rope_k<<<dim3((nrope + 255)/256, 2), 256>>>(q_, k_, cs, sn);
    // 4. attention -> y [B,T,H,HD]
    attn_k<<<dim3(TT/64, BB*HH), 256>>>(q_, k_, v_, y_);
    // 5. x2 = x + y @ wo
    tfgemm_k<1><<<gemm_cc, 256>>>(y_, wo, wo, wo, x2_, x2_, x2_, x, MROWS, CC, CC);
    // 6. h = rmsnorm(x2, g2)
    rmsnorm_k<<<MROWS, 256>>>(x2_, g2, h_);
    // 7. a = relu(h @ wfc)^2
    tfgemm_k<2><<<gemm_ff, 256>>>(h_, wfc, wfc, wfc, a_, a_, a_, nullptr, MROWS, FF, CC);
    // 8. out = x2 + a @ wpr
    tfgemm_k<1><<<gemm_cc, 256>>>(a_, wpr, wpr, wpr, out, out, out, x2_, MROWS, CC, FF);
}

// round 8
// speedup vs baseline: 2.1898x; 1.2197x over previous
#include <cuda_runtime.h>
#include <cuda_bf16.h>
#include <math.h>

// Problem constants
#define BB 2
#define TT 2048
#define CC 768
#define HH 12
#define HD 64
#define D2 32
#define FF 3072
#define MROWS (BB*TT)          // 4096
#define EPSV 1e-5f

// ---------------- scratch ---------------------------------------------------
__device__ float g_h [MROWS*CC];
__device__ float g_q [MROWS*CC];
__device__ float g_k [MROWS*CC];
__device__ float g_v [MROWS*CC];
__device__ float g_y [MROWS*CC];
__device__ float g_x2[MROWS*CC];
__device__ float g_a [MROWS*FF];

// ---------------- helpers ---------------------------------------------------
__device__ __forceinline__ unsigned f2tf(float f) {
    unsigned u;
    asm("cvt.rna.tf32.f32 %0, %1;" : "=r"(u) : "f"(f));
    return u;
}
__device__ __forceinline__ void mma_tf32(float* c, const unsigned* a, const unsigned* b) {
    asm("mma.sync.aligned.m16n8k8.row.col.f32.tf32.tf32.f32 "
        "{%0,%1,%2,%3},{%4,%5,%6,%7},{%8,%9},{%0,%1,%2,%3};"
        : "+f"(c[0]), "+f"(c[1]), "+f"(c[2]), "+f"(c[3])
        : "r"(a[0]), "r"(a[1]), "r"(a[2]), "r"(a[3]), "r"(b[0]), "r"(b[1]));
}
__device__ __forceinline__ void cp_async16(unsigned dst, const void* src) {
    asm volatile("cp.async.cg.shared.global [%0], [%1], 16;" :: "r"(dst), "l"(src));
}
__device__ __forceinline__ void cp_commit() {
    asm volatile("cp.async.commit_group;");
}
__device__ __forceinline__ void cp_wait0() {
    asm volatile("cp.async.wait_group 0;");
}

// ---------------- RMSNorm ---------------------------------------------------
__global__ void rmsnorm_k(const float* __restrict__ x, const float* __restrict__ g,
                          float* __restrict__ o) {
    int row = blockIdx.x;
    int tid = threadIdx.x;            // 256 threads
    const float* xr = x + (size_t)row * CC;
    float v0 = xr[tid], v1 = xr[tid + 256], v2 = xr[tid + 512];
    float ss = v0*v0 + v1*v1 + v2*v2;
    #pragma unroll
    for (int m = 16; m > 0; m >>= 1) ss += __shfl_xor_sync(0xffffffffu, ss, m);
    __shared__ float ws[8];
    if ((tid & 31) == 0) ws[tid >> 5] = ss;
    __syncthreads();
    float tot = 0.f;
    #pragma unroll
    for (int i = 0; i < 8; i++) tot += ws[i];
    float sc = rsqrtf(tot * (1.0f / CC) + EPSV);
    float* orow = o + (size_t)row * CC;
    orow[tid      ] = g[tid      ] * v0 * sc;
    orow[tid + 256] = g[tid + 256] * v1 * sc;
    orow[tid + 512] = g[tid + 512] * v2 * sc;
}

// ---------------- RoPE in-place, q and k in one launch (y) ------------------
__global__ void rope_k(float* __restrict__ q, float* __restrict__ k,
                       const float* __restrict__ cs, const float* __restrict__ sn) {
    int idx = blockIdx.x * blockDim.x + threadIdx.x;   // over B*T*H*D2
    if (idx >= BB*TT*HH*D2) return;
    float* base = (blockIdx.y == 0) ? q : k;
    int d = idx & (D2 - 1);
    int h = (idx / D2) % HH;
    int t = (idx / (D2 * HH)) % TT;
    int b = idx / (D2 * HH * TT);
    float* p = base + (((size_t)(b*TT + t))*HH + h) * HD;
    float c = cs[t*D2 + d], s = sn[t*D2 + d];
    float x1 = p[d], x2 = p[d + D2];
    p[d]      =  x1 * c + x2 * s;
    p[d + D2] = -x1 * s + x2 * c;
}

// ---------------- TF32 tensor-core GEMM 128x128x16, pipelined ---------------
template<int EPI>
__global__ void __launch_bounds__(256)
tfgemm_k(const float* __restrict__ A,
         const float* __restrict__ B0, const float* __restrict__ B1,
         const float* __restrict__ B2,
         float* __restrict__ C0, float* __restrict__ C1, float* __restrict__ C2,
         const float* __restrict__ R, int M, int N, int K) {
    __shared__ unsigned As[2][2048];
    __shared__ unsigned Bs[2][2048];
    const int tid  = threadIdx.x;
    const int warp = tid >> 5, lane = tid & 31;
    const int wm = warp >> 2, wn = warp & 3;
    const int bm = blockIdx.y * 128, bn = blockIdx.x * 128;
    const float* Bsel = (blockIdx.z == 0) ? B0 : ((blockIdx.z == 1) ? B1 : B2);
    float*       Csel = (blockIdx.z == 0) ? C0 : ((blockIdx.z == 1) ? C1 : C2);
    const float* Ab = A + (size_t)bm * K;
    const float* Bb = Bsel + bn;

    float acc[4][4][4];
    #pragma unroll
    for (int i = 0; i < 4; i++)
        #pragma unroll
        for (int j = 0; j < 4; j++)
            #pragma unroll
            for (int t = 0; t < 4; t++) acc[i][j][t] = 0.f;

    float4 r0a[2], r0b[2], r1a[2], r1b[2];
    const int NB = K >> 4;

    #define LDG_STAGE(kb, ra, rb)                                                \
        _Pragma("unroll")                                                        \
        for (int it = 0; it < 2; it++) {                                         \
            int idx = it*256 + tid;                                              \
            int m = idx >> 2, k4 = idx & 3;                                      \
            ra[it] = *(const float4*)(Ab + (size_t)m*K + (kb)*16 + k4*4);        \
            int kr = idx >> 5, n4 = idx & 31;                                    \
            rb[it] = *(const float4*)(Bb + (size_t)((kb)*16 + kr)*N + n4*4);     \
        }

    #define STS_STAGE(buf, ra, rb)                                               \
        _Pragma("unroll")                                                        \
        for (int it = 0; it < 2; it++) {                                         \
            int idx = it*256 + tid;                                              \
            int m = idx >> 2, k4 = idx & 3;                                      \
            int mt = m >> 4, row = m & 15;                                       \
            int kt = k4 >> 1;                                                    \
            int slot = ((row & 8) ? 1 : 0) + ((k4 & 1) ? 2 : 0);                 \
            int ln0 = (row & 7) * 4;                                             \
            unsigned* ab = &As[buf][(kt*8 + mt)*128 + slot];                     \
            const float* av = (const float*)&ra[it];                             \
            _Pragma("unroll")                                                    \
            for (int j = 0; j < 4; j++) ab[(ln0 + j)*4] = f2tf(av[j]);           \
            int kr = idx >> 5, n4 = idx & 31;                                    \
            int kt2 = kr >> 3, kr8 = kr & 7;                                     \
            int bslot = (kr8 >= 4) ? 1 : 0, kin = kr8 & 3;                       \
            int nt = n4 >> 1;                                                    \
            unsigned* bb = &Bs[buf][(kt2*16 + nt)*64 + bslot];                   \
            const float* bv = (const float*)&rb[it];                             \
            _Pragma("unroll")                                                    \
            for (int j = 0; j < 4; j++) {                                        \
                int ln = ((n4 & 1)*4 + j)*4 + kin;                               \
                bb[ln*2] = f2tf(bv[j]);                                          \
            }                                                                    \
        }

    #define MMA_STAGE(buf)                                                       \
        _Pragma("unroll")                                                        \
        for (int kt = 0; kt < 2; kt++) {                                         \
            unsigned a[4][4], b[4][2];                                           \
            _Pragma("unroll")                                                    \
            for (int i = 0; i < 4; i++)                                          \
                *(uint4*)a[i] =                                                  \
                    *(const uint4*)&As[buf][(kt*8 + wm*4 + i)*128 + lane*4];     \
            _Pragma("unroll")                                                    \
            for (int j = 0; j < 4; j++) {                                        \
                uint2 bv =                                                       \
                    *(const uint2*)&Bs[buf][(kt*16 + wn*4 + j)*64 + lane*2];     \
                b[j][0] = bv.x; b[j][1] = bv.y;                                  \
            }                                                                    \
            _Pragma("unroll")                                                    \
            for (int i = 0; i < 4; i++)                                          \
                _Pragma("unroll")                                                \
                for (int j = 0; j < 4; j++)                                      \
                    mma_tf32(acc[i][j], a[i], b[j]);                             \
        }

    LDG_STAGE(0, r0a, r0b)
    STS_STAGE(0, r0a, r0b)
    LDG_STAGE(1, r1a, r1b)
    __syncthreads();

    for (int kb = 0; kb < NB; kb += 2) {
        STS_STAGE(1, r1a, r1b)
        if (kb + 2 < NB) { LDG_STAGE(kb + 2, r0a, r0b) }
        MMA_STAGE(0)
        __syncthreads();
        if (kb + 2 < NB) {
            STS_STAGE(0, r0a, r0b)
            if (kb + 3 < NB) { LDG_STAGE(kb + 3, r1a, r1b) }
        }
        MMA_STAGE(1)
        __syncthreads();
    }

    #pragma unroll
    for (int i = 0; i < 4; i++) {
        int r = bm + (wm*4 + i)*16 + (lane >> 2);
        #pragma unroll
        for (int j = 0; j < 4; j++) {
            int c = bn + (wn*4 + j)*8 + (lane & 3)*2;
            float2 v0 = make_float2(acc[i][j][0], acc[i][j][1]);
            float2 v1 = make_float2(acc[i][j][2], acc[i][j][3]);
            if (EPI == 1) {
                float2 rr0 = *(const float2*)(R + (size_t)r*N + c);
                float2 rr1 = *(const float2*)(R + (size_t)(r+8)*N + c);
                v0.x += rr0.x; v0.y += rr0.y;
                v1.x += rr1.x; v1.y += rr1.y;
            } else if (EPI == 2) {
                v0.x = fmaxf(v0.x, 0.f); v0.x *= v0.x;
                v0.y = fmaxf(v0.y, 0.f); v0.y *= v0.y;
                v1.x = fmaxf(v1.x, 0.f); v1.x *= v1.x;
                v1.y = fmaxf(v1.y, 0.f); v1.y *= v1.y;
            }
            *(float2*)(Csel + (size_t)r*N + c)     = v0;
            *(float2*)(Csel + (size_t)(r+8)*N + c) = v1;
        }
    }
    #undef LDG_STAGE
    #undef STS_STAGE
    #undef MMA_STAGE
}

// ---------------- TF32 tensor-core flash attention --------------------------
// Block: 64 q rows, 128 threads (4 warps); warp w owns rows w*16..w*16+15.
// Q A-frags in regs; K/V tiles (64 keys) via cp.async double buffer.
// S = Q K^T via mma.m16n8k8; softmax on C-frags (quad shuffles);
// P C-frag -> A-frag via lane shuffles; O += P V via mma. fp32 bits fed
// directly as tf32 operands (HW truncates mantissa).
#define PADK 68
#define PADV 72
#define KWORDS (64*PADK)            // 4352
#define VWORDS (64*PADV)            // 4608
#define BUFW   (KWORDS + VWORDS)    // 8960
#define ATTN_SMEM (2*BUFW*4)        // 71680 bytes

extern __shared__ float attn_sm[];

__global__ void __launch_bounds__(128)
attn_tc_k(const float* __restrict__ Q, const float* __restrict__ K,
          const float* __restrict__ V, float* __restrict__ Y) {
    const int qb  = blockIdx.x;          // 0..31 (64 q rows each)
    const int bh  = blockIdx.y;
    const int b   = bh / HH, h = bh % HH;
    const int tid = threadIdx.x;
    const int lane = tid & 31, w = tid >> 5;
    const int g = lane >> 2, q = lane & 3;
    const size_t base = (((size_t)b * TT) * HH + h) * HD;
    const float* Qg = Q + base;
    const float* Kg = K + base;
    const float* Vg = V + base;
    unsigned sbase = (unsigned)__cvta_generic_to_shared(attn_sm);

    // ---- stage Q tile into buf0 K region, read A-frags to regs ------------
    #pragma unroll
    for (int it = 0; it < 8; it++) {
        int idx = it*128 + tid;
        int r = idx >> 4, c4 = idx & 15;
        cp_async16(sbase + (unsigned)(r*PADK + c4*4)*4u,
                   Qg + (size_t)(qb*64 + r)*(HH*HD) + c4*4);
    }
    cp_commit();
    cp_wait0();
    __syncthreads();

    unsigned qa[8][4];
    #pragma unroll
    for (int kf = 0; kf < 8; kf++) {
        qa[kf][0] = __float_as_uint(attn_sm[(w*16 + g    )*PADK + kf*8 + q    ]);
        qa[kf][1] = __float_as_uint(attn_sm[(w*16 + g + 8)*PADK + kf*8 + q    ]);
        qa[kf][2] = __float_as_uint(attn_sm[(w*16 + g    )*PADK + kf*8 + q + 4]);
        qa[kf][3] = __float_as_uint(attn_sm[(w*16 + g + 8)*PADK + kf*8 + q + 4]);
    }
    __syncthreads();

    #define ISSUE_TILE(kb, bufsel)                                              \
        {                                                                       \
            unsigned kd = sbase + (unsigned)(bufsel)*(BUFW*4u);                 \
            _Pragma("unroll")                                                   \
            for (int it = 0; it < 8; it++) {                                    \
                int idx = it*128 + tid;                                         \
                int r = idx >> 4, c4 = idx & 15;                                \
                const float* ksrc = Kg + (size_t)((kb)*64 + r)*(HH*HD) + c4*4;  \
                const float* vsrc = Vg + (size_t)((kb)*64 + r)*(HH*HD) + c4*4;  \
                cp_async16(kd + (unsigned)(r*PADK + c4*4)*4u, ksrc);            \
                cp_async16(kd + (unsigned)(KWORDS + r*PADV + c4*4)*4u, vsrc);   \
            }                                                                   \
            cp_commit();                                                        \
        }

    ISSUE_TILE(0, 0)

    float m0 = -1e30f, m1 = -1e30f, l0 = 0.f, l1 = 0.f;
    float o[8][4];
    #pragma unroll
    for (int nt = 0; nt < 8; nt++)
        #pragma unroll
        for (int t = 0; t < 4; t++) o[nt][t] = 0.f;

    const float scale = 0.125f;   // 1/sqrt(64)

    for (int kb = 0; kb <= qb; kb++) {
        cp_wait0();
        __syncthreads();           // tile kb visible; prev compute done on other buf
        if (kb + 1 <= qb) { ISSUE_TILE(kb + 1, (kb + 1) & 1) }

        const float* Ks = attn_sm + (kb & 1)*BUFW;
        const float* Vs = Ks + KWORDS;

        // ---- S = Q K^T -----------------------------------------------------
        float s[8][4];
        #pragma unroll
        for (int nt = 0; nt < 8; nt++)
            #pragma unroll
            for (int t = 0; t < 4; t++) s[nt][t] = 0.f;
        #pragma unroll
        for (int kf = 0; kf < 8; kf++) {
            #pragma unroll
            for (int nt = 0; nt < 8; nt++) {
                unsigned bb[2];
                bb[0] = __float_as_uint(Ks[(nt*8 + g)*PADK + kf*8 + q    ]);
                bb[1] = __float_as_uint(Ks[(nt*8 + g)*PADK + kf*8 + q + 4]);
                mma_tf32(s[nt], qa[kf], bb);
            }
        }

        // ---- scale + causal mask (diagonal tile only) ----------------------
        #pragma unroll
        for (int nt = 0; nt < 8; nt++) {
            s[nt][0] *= scale; s[nt][1] *= scale;
            s[nt][2] *= scale; s[nt][3] *= scale;
        }
        if (kb == qb) {
            int rl0 = w*16 + g, rl1 = rl0 + 8;
            #pragma unroll
            for (int nt = 0; nt < 8; nt++) {
                int c0 = nt*8 + 2*q, c1 = c0 + 1;
                if (c0 > rl0) s[nt][0] = -1e30f;
                if (c1 > rl0) s[nt][1] = -1e30f;
                if (c0 > rl1) s[nt][2] = -1e30f;
                if (c1 > rl1) s[nt][3] = -1e30f;
            }
        }

        // ---- online softmax (rows r0 = regs 0,1; r1 = regs 2,3) -----------
        float tm0 = -1e30f, tm1 = -1e30f;
        #pragma unroll
        for (int nt = 0; nt < 8; nt++) {
            tm0 = fmaxf(tm0, fmaxf(s[nt][0], s[nt][1]));
            tm1 = fmaxf(tm1, fmaxf(s[nt][2], s[nt][3]));
        }
        tm0 = fmaxf(tm0, __shfl_xor_sync(0xffffffffu, tm0, 1));
        tm0 = fmaxf(tm0, __shfl_xor_sync(0xffffffffu, tm0, 2));
        tm1 = fmaxf(tm1, __shfl_xor_sync(0xffffffffu, tm1, 1));
        tm1 = fmaxf(tm1, __shfl_xor_sync(0xffffffffu, tm1, 2));
        float mn0 = fmaxf(m0, tm0), mn1 = fmaxf(m1, tm1);
        float f0 = __expf(m0 - mn0), f1 = __expf(m1 - mn1);
        m0 = mn0; m1 = mn1;
        float sum0 = 0.f, sum1 = 0.f;
        #pragma unroll
        for (int nt = 0; nt < 8; nt++) {
            s[nt][0] = __expf(s[nt][0] - mn0); sum0 += s[nt][0];
            s[nt][1] = __expf(s[nt][1] - mn0); sum0 += s[nt][1];
            s[nt][2] = __expf(s[nt][2] - mn1); sum1 += s[nt][2];
            s[nt][3] = __expf(s[nt][3] - mn1); sum1 += s[nt][3];
        }
        sum0 += __shfl_xor_sync(0xffffffffu, sum0, 1);
        sum0 += __shfl_xor_sync(0xffffffffu, sum0, 2);
        sum1 += __shfl_xor_sync(0xffffffffu, sum1, 1);
        sum1 += __shfl_xor_sync(0xffffffffu, sum1, 2);
        l0 = l0*f0 + sum0;
        l1 = l1*f1 + sum1;
        #pragma unroll
        for (int nt = 0; nt < 8; nt++) {
            o[nt][0] *= f0; o[nt][1] *= f0;
            o[nt][2] *= f1; o[nt][3] *= f1;
        }

        // ---- O += P V : P C-frag -> A-frag via quad shuffles ---------------
        #pragma unroll
        for (int kf = 0; kf < 8; kf++) {
            int src0 = (lane & ~3) | (q >> 1);
            float v00 = __shfl_sync(0xffffffffu, s[kf][0], src0);
            float v01 = __shfl_sync(0xffffffffu, s[kf][1], src0);
            float v10 = __shfl_sync(0xffffffffu, s[kf][2], src0);
            float v11 = __shfl_sync(0xffffffffu, s[kf][3], src0);
            float v20 = __shfl_sync(0xffffffffu, s[kf][0], src0 + 2);
            float v21 = __shfl_sync(0xffffffffu, s[kf][1], src0 + 2);
            float v30 = __shfl_sync(0xffffffffu, s[kf][2], src0 + 2);
            float v31 = __shfl_sync(0xffffffffu, s[kf][3], src0 + 2);
            unsigned pa[4];
            pa[0] = __float_as_uint((q & 1) ? v01 : v00);
            pa[1] = __float_as_uint((q & 1) ? v11 : v10);
            pa[2] = __float_as_uint((q & 1) ? v21 : v20);
            pa[3] = __float_as_uint((q & 1) ? v31 : v30);
            #pragma unroll
            for (int nt = 0; nt < 8; nt++) {
                unsigned vb[2];
                vb[0] = __float_as_uint(Vs[(kf*8 + q    )*PADV + nt*8 + g]);
                vb[1] = __float_as_uint(Vs[(kf*8 + q + 4)*PADV + nt*8 + g]);
                mma_tf32(o[nt], pa, vb);
            }
        }
    }

    // ---- epilogue ----------------------------------------------------------
    float inv0 = 1.0f / l0, inv1 = 1.0f / l1;
    int r0 = qb*64 + w*16 + g, r1 = r0 + 8;
    #pragma unroll
    for (int nt = 0; nt < 8; nt++) {
        float2 v0 = make_float2(o[nt][0]*inv0, o[nt][1]*inv0);
        float2 v1 = make_float2(o[nt][2]*inv1, o[nt][3]*inv1);
        *(float2*)(Y + base + (size_t)r0*(HH*HD) + nt*8 + 2*q) = v0;
        *(float2*)(Y + base + (size_t)r1*(HH*HD) + nt*8 + 2*q) = v1;
    }
    #undef ISSUE_TILE
}

// ---------------- launch ----------------------------------------------------
extern "C" void kernel_launch(void* const* d_in, const int* in_sizes, int n_in,
                              void* d_out, int out_size) {
    const float* x   = (const float*)d_in[0];
    const float* cs  = (const float*)d_in[1];
    const float* sn  = (const float*)d_in[2];
    const float* wq  = (const float*)d_in[3];
    const float* wk  = (const float*)d_in[4];
    const float* wv  = (const float*)d_in[5];
    const float* wo  = (const float*)d_in[6];
    const float* wfc = (const float*)d_in[7];
    const float* wpr = (const float*)d_in[8];
    const float* g1  = (const float*)d_in[9];
    const float* g2  = (const float*)d_in[10];
    float* out = (float*)d_out;

    float *h_, *q_, *k_, *v_, *y_, *x2_, *a_;
    cudaGetSymbolAddress((void**)&h_,  g_h);
    cudaGetSymbolAddress((void**)&q_,  g_q);
    cudaGetSymbolAddress((void**)&k_,  g_k);
    cudaGetSymbolAddress((void**)&v_,  g_v);
    cudaGetSymbolAddress((void**)&y_,  g_y);
    cudaGetSymbolAddress((void**)&x2_, g_x2);
    cudaGetSymbolAddress((void**)&a_,  g_a);

    cudaFuncSetAttribute(attn_tc_k, cudaFuncAttributeMaxDynamicSharedMemorySize,
                         ATTN_SMEM);

    dim3 gemm_qkv(CC/128, MROWS/128, 3);  // (6, 32, 3) fused QKV
    dim3 gemm_cc (CC/128, MROWS/128, 1);  // (6, 32)
    dim3 gemm_ff (FF/128, MROWS/128, 1);  // (24, 32)

    // 1. h = rmsnorm(x, g1)
    rmsnorm_k<<<MROWS, 256>>>(x, g1, h_);
    // 2. q,k,v = h @ w{q,k,v}  (one fused launch)
    tfgemm_k<0><<<gemm_qkv, 256>>>(h_, wq, wk, wv, q_, k_, v_, nullptr, MROWS, CC, CC);
    // 3. RoPE on q and k (one launch)
    int nrope = BB*TT*HH*D2;
    rope_k<<<dim3((nrope + 255)/256, 2), 256>>>(q_, k_, cs, sn);
    // 4. attention -> y [B,T,H,HD]  (tensor-core flash)
    attn_tc_k<<<dim3(TT/64, BB*HH), 128, ATTN_SMEM>>>(q_, k_, v_, y_);
    // 5. x2 = x + y @ wo
    tfgemm_k<1><<<gemm_cc, 256>>>(y_, wo, wo, wo, x2_, x2_, x2_, x, MROWS, CC, CC);
    // 6. h = rmsnorm(x2, g2)
    rmsnorm_k<<<MROWS, 256>>>(x2_, g2, h_);
    // 7. a = relu(h @ wfc)^2
    tfgemm_k<2><<<gemm_ff, 256>>>(h_, wfc, wfc, wfc, a_, a_, a_, nullptr, MROWS, FF, CC);
    // 8. out = x2 + a @ wpr
    tfgemm_k<1><<<gemm_cc, 256>>>(a_, wpr, wpr, wpr, out, out, out, x2_, MROWS, CC, FF);
}

// round 10
// speedup vs baseline: 6.0999x; 2.7856x over previous
#include <cuda_runtime.h>
#include <cuda_bf16.h>
#include <math.h>

// Problem constants
#define BB 2
#define TT 2048
#define CC 768
#define HH 12
#define HD 64
#define D2 32
#define FF 3072
#define MROWS (BB*TT)          // 4096
#define EPSV 1e-5f

// ---------------- scratch ---------------------------------------------------
__device__ float g_h [MROWS*CC];
__device__ float g_q [MROWS*CC];
__device__ float g_k [MROWS*CC];
__device__ float g_v [MROWS*CC];
__device__ float g_y [MROWS*CC];
__device__ float g_x2[MROWS*CC];
__device__ float g_a [MROWS*FF];

// ---------------- helpers ---------------------------------------------------
__device__ __forceinline__ void mma_tf32(float* c, const unsigned* a, const unsigned* b) {
    asm("mma.sync.aligned.m16n8k8.row.col.f32.tf32.tf32.f32 "
        "{%0,%1,%2,%3},{%4,%5,%6,%7},{%8,%9},{%0,%1,%2,%3};"
        : "+f"(c[0]), "+f"(c[1]), "+f"(c[2]), "+f"(c[3])
        : "r"(a[0]), "r"(a[1]), "r"(a[2]), "r"(a[3]), "r"(b[0]), "r"(b[1]));
}
__device__ __forceinline__ void cp_async16(unsigned dst, const void* src) {
    asm volatile("cp.async.cg.shared.global [%0], [%1], 16;" :: "r"(dst), "l"(src));
}
__device__ __forceinline__ void cp_commit() {
    asm volatile("cp.async.commit_group;");
}
template<int N>
__device__ __forceinline__ void cp_wait() {
    asm volatile("cp.async.wait_group %0;" :: "n"(N));
}

// ---------------- RMSNorm ---------------------------------------------------
__global__ void rmsnorm_k(const float* __restrict__ x, const float* __restrict__ g,
                          float* __restrict__ o) {
    int row = blockIdx.x;
    int tid = threadIdx.x;            // 256 threads
    const float* xr = x + (size_t)row * CC;
    float v0 = xr[tid], v1 = xr[tid + 256], v2 = xr[tid + 512];
    float ss = v0*v0 + v1*v1 + v2*v2;
    #pragma unroll
    for (int m = 16; m > 0; m >>= 1) ss += __shfl_xor_sync(0xffffffffu, ss, m);
    __shared__ float ws[8];
    if ((tid & 31) == 0) ws[tid >> 5] = ss;
    __syncthreads();
    float tot = 0.f;
    #pragma unroll
    for (int i = 0; i < 8; i++) tot += ws[i];
    float sc = rsqrtf(tot * (1.0f / CC) + EPSV);
    float* orow = o + (size_t)row * CC;
    orow[tid      ] = g[tid      ] * v0 * sc;
    orow[tid + 256] = g[tid + 256] * v1 * sc;
    orow[tid + 512] = g[tid + 512] * v2 * sc;
}

// ---------------- RoPE in-place, q and k in one launch (y) ------------------
__global__ void rope_k(float* __restrict__ q, float* __restrict__ k,
                       const float* __restrict__ cs, const float* __restrict__ sn) {
    int idx = blockIdx.x * blockDim.x + threadIdx.x;   // over B*T*H*D2
    if (idx >= BB*TT*HH*D2) return;
    float* base = (blockIdx.y == 0) ? q : k;
    int d = idx & (D2 - 1);
    int h = (idx / D2) % HH;
    int t = (idx / (D2 * HH)) % TT;
    int b = idx / (D2 * HH * TT);
    float* p = base + (((size_t)(b*TT + t))*HH + h) * HD;
    float c = cs[t*D2 + d], s = sn[t*D2 + d];
    float x1 = p[d], x2 = p[d + D2];
    p[d]      =  x1 * c + x2 * s;
    p[d + D2] = -x1 * s + x2 * c;
}

// ---------------- TF32 tensor-core GEMM, cp.async 3-stage -------------------
// 256 threads = 8 warps in 2(M) x 4(N); warp tile 64x32; mma.m16n8k8.
// Row-major padded smem; raw fp32 bits fed as tf32 (HW truncates).
// A-frag gather (g*20+q) and B-frag gather (q*136+g) are conflict-free.
// One __syncthreads per 16-K block; cp.async keeps next stage in flight.
// blockIdx.z selects among (B0,C0)/(B1,C1)/(B2,C2) for fused QKV.
// EPI: 0 = plain, 1 = +residual R, 2 = relu(x)^2
#define AS_STRIDE 20                 // 16 + 4 pad
#define BS_STRIDE 136                // 128 + 8 pad
#define AS_WORDS (128*AS_STRIDE)     // 2560
#define BS_WORDS (16*BS_STRIDE)      // 2176
#define STG_WORDS (AS_WORDS + BS_WORDS)   // 4736
#define GEMM_SMEM (3*STG_WORDS*4)    // 56832 bytes

extern __shared__ float gemm_sm[];

template<int EPI>
__global__ void __launch_bounds__(256, 2)
tfgemm_k(const float* __restrict__ A,
         const float* __restrict__ B0, const float* __restrict__ B1,
         const float* __restrict__ B2,
         float* __restrict__ C0, float* __restrict__ C1, float* __restrict__ C2,
         const float* __restrict__ R, int M, int N, int K) {
    const int tid  = threadIdx.x;
    const int warp = tid >> 5, lane = tid & 31;
    const int wm = warp >> 2, wn = warp & 3;
    const int g = lane >> 2, q = lane & 3;
    const int bm = blockIdx.y * 128, bn = blockIdx.x * 128;
    const float* Bsel = (blockIdx.z == 0) ? B0 : ((blockIdx.z == 1) ? B1 : B2);
    float*       Csel = (blockIdx.z == 0) ? C0 : ((blockIdx.z == 1) ? C1 : C2);
    const float* Ab = A + (size_t)bm * K;
    const float* Bb = Bsel + bn;
    unsigned sbase = (unsigned)__cvta_generic_to_shared(gemm_sm);

    float acc[4][4][4];
    #pragma unroll
    for (int i = 0; i < 4; i++)
        #pragma unroll
        for (int j = 0; j < 4; j++)
            #pragma unroll
            for (int t = 0; t < 4; t++) acc[i][j][t] = 0.f;

    const int NB = K >> 4;            // 48 or 192

    // per-thread cp.async coordinates (fixed)
    // A tile 128x16: 512 chunks; chunk idx -> m = idx>>2, k4 = idx&3
    // B tile 16x128: 512 chunks; chunk idx -> kr = idx>>5, n4 = idx&31
    #define ISSUE_STAGE(kb, st)                                                  \
        {                                                                        \
            unsigned sd = sbase + (unsigned)(st)*(STG_WORDS*4u);                 \
            _Pragma("unroll")                                                    \
            for (int it = 0; it < 2; it++) {                                     \
                int idx = it*256 + tid;                                          \
                int m = idx >> 2, k4 = idx & 3;                                  \
                cp_async16(sd + (unsigned)(m*AS_STRIDE + k4*4)*4u,               \
                           Ab + (size_t)m*K + (kb)*16 + k4*4);                   \
                int kr = idx >> 5, n4 = idx & 31;                                \
                cp_async16(sd + (unsigned)(AS_WORDS + kr*BS_STRIDE + n4*4)*4u,   \
                           Bb + (size_t)((kb)*16 + kr)*N + n4*4);                \
            }                                                                    \
            cp_commit();                                                         \
        }

    ISSUE_STAGE(0, 0)
    ISSUE_STAGE(1, 1)

    int st = 0;
    for (int kb = 0; kb < NB; kb++) {
        cp_wait<1>();                 // stage kb resident
        __syncthreads();              // all warps past compute kb-1 (buf st+2)
        if (kb + 2 < NB) {
            int st2 = st + 2; if (st2 >= 3) st2 -= 3;
            ISSUE_STAGE(kb + 2, st2)
        }
        const float* As = gemm_sm + st*STG_WORDS;
        const float* Bs = As + AS_WORDS;
        #pragma unroll
        for (int kt = 0; kt < 2; kt++) {
            unsigned a[4][4], b[4][2];
            #pragma unroll
            for (int i = 0; i < 4; i++) {
                const float* ar = As + (wm*64 + i*16)*AS_STRIDE + kt*8;
                a[i][0] = __float_as_uint(ar[(g    )*AS_STRIDE + q    ]);
                a[i][1] = __float_as_uint(ar[(g + 8)*AS_STRIDE + q    ]);
                a[i][2] = __float_as_uint(ar[(g    )*AS_STRIDE + q + 4]);
                a[i][3] = __float_as_uint(ar[(g + 8)*AS_STRIDE + q + 4]);
            }
            #pragma unroll
            for (int j = 0; j < 4; j++) {
                const float* br = Bs + kt*8*BS_STRIDE + wn*32 + j*8 + g;
                b[j][0] = __float_as_uint(br[(q    )*BS_STRIDE]);
                b[j][1] = __float_as_uint(br[(q + 4)*BS_STRIDE]);
            }
            #pragma unroll
            for (int i = 0; i < 4; i++)
                #pragma unroll
                for (int j = 0; j < 4; j++)
                    mma_tf32(acc[i][j], a[i], b[j]);
        }
        st++; if (st >= 3) st = 0;
    }

    // epilogue (acc layout: c0,c1 -> row g; c2,c3 -> row g+8; cols 2q,2q+1)
    #pragma unroll
    for (int i = 0; i < 4; i++) {
        int r = bm + wm*64 + i*16 + g;
        #pragma unroll
        for (int j = 0; j < 4; j++) {
            int c = bn + wn*32 + j*8 + 2*q;
            float2 v0 = make_float2(acc[i][j][0], acc[i][j][1]);
            float2 v1 = make_float2(acc[i][j][2], acc[i][j][3]);
            if (EPI == 1) {
                float2 rr0 = *(const float2*)(R + (size_t)r*N + c);
                float2 rr1 = *(const float2*)(R + (size_t)(r+8)*N + c);
                v0.x += rr0.x; v0.y += rr0.y;
                v1.x += rr1.x; v1.y += rr1.y;
            } else if (EPI == 2) {
                v0.x = fmaxf(v0.x, 0.f); v0.x *= v0.x;
                v0.y = fmaxf(v0.y, 0.f); v0.y *= v0.y;
                v1.x = fmaxf(v1.x, 0.f); v1.x *= v1.x;
                v1.y = fmaxf(v1.y, 0.f); v1.y *= v1.y;
            }
            *(float2*)(Csel + (size_t)r*N + c)     = v0;
            *(float2*)(Csel + (size_t)(r+8)*N + c) = v1;
        }
    }
    #undef ISSUE_STAGE
}

// ---------------- TF32 tensor-core flash attention --------------------------
#define PADK 68
#define PADV 72
#define KWORDS (64*PADK)            // 4352
#define VWORDS (64*PADV)            // 4608
#define BUFW   (KWORDS + VWORDS)    // 8960
#define ATTN_SMEM (2*BUFW*4)        // 71680 bytes

extern __shared__ float attn_sm[];

__global__ void __launch_bounds__(128)
attn_tc_k(const float* __restrict__ Q, const float* __restrict__ K,
          const float* __restrict__ V, float* __restrict__ Y) {
    const int qb  = blockIdx.x;          // 0..31 (64 q rows each)
    const int bh  = blockIdx.y;
    const int b   = bh / HH, h = bh % HH;
    const int tid = threadIdx.x;
    const int lane = tid & 31, w = tid >> 5;
    const int g = lane >> 2, q = lane & 3;
    const size_t base = (((size_t)b * TT) * HH + h) * HD;
    const float* Qg = Q + base;
    const float* Kg = K + base;
    const float* Vg = V + base;
    unsigned sbase = (unsigned)__cvta_generic_to_shared(attn_sm);

    // ---- stage Q tile into buf0 K region, read A-frags to regs ------------
    #pragma unroll
    for (int it = 0; it < 8; it++) {
        int idx = it*128 + tid;
        int r = idx >> 4, c4 = idx & 15;
        cp_async16(sbase + (unsigned)(r*PADK + c4*4)*4u,
                   Qg + (size_t)(qb*64 + r)*(HH*HD) + c4*4);
    }
    cp_commit();
    cp_wait<0>();
    __syncthreads();

    unsigned qa[8][4];
    #pragma unroll
    for (int kf = 0; kf < 8; kf++) {
        qa[kf][0] = __float_as_uint(attn_sm[(w*16 + g    )*PADK + kf*8 + q    ]);
        qa[kf][1] = __float_as_uint(attn_sm[(w*16 + g + 8)*PADK + kf*8 + q    ]);
        qa[kf][2] = __float_as_uint(attn_sm[(w*16 + g    )*PADK + kf*8 + q + 4]);
        qa[kf][3] = __float_as_uint(attn_sm[(w*16 + g + 8)*PADK + kf*8 + q + 4]);
    }
    __syncthreads();

    #define ISSUE_TILE(kb, bufsel)                                              \
        {                                                                       \
            unsigned kd = sbase + (unsigned)(bufsel)*(BUFW*4u);                 \
            _Pragma("unroll")                                                   \
            for (int it = 0; it < 8; it++) {                                    \
                int idx = it*128 + tid;                                         \
                int r = idx >> 4, c4 = idx & 15;                                \
                const float* ksrc = Kg + (size_t)((kb)*64 + r)*(HH*HD) + c4*4;  \
                const float* vsrc = Vg + (size_t)((kb)*64 + r)*(HH*HD) + c4*4;  \
                cp_async16(kd + (unsigned)(r*PADK + c4*4)*4u, ksrc);            \
                cp_async16(kd + (unsigned)(KWORDS + r*PADV + c4*4)*4u, vsrc);   \
            }                                                                   \
            cp_commit();                                                        \
        }

    ISSUE_TILE(0, 0)

    float m0 = -1e30f, m1 = -1e30f, l0 = 0.f, l1 = 0.f;
    float o[8][4];
    #pragma unroll
    for (int nt = 0; nt < 8; nt++)
        #pragma unroll
        for (int t = 0; t < 4; t++) o[nt][t] = 0.f;

    const float scale = 0.125f;   // 1/sqrt(64)

    for (int kb = 0; kb <= qb; kb++) {
        cp_wait<0>();
        __syncthreads();           // tile kb visible; prev compute done on other buf
        if (kb + 1 <= qb) { ISSUE_TILE(kb + 1, (kb + 1) & 1) }

        const float* Ks = attn_sm + (kb & 1)*BUFW;
        const float* Vs = Ks + KWORDS;

        // ---- S = Q K^T -----------------------------------------------------
        float s[8][4];
        #pragma unroll
        for (int nt = 0; nt < 8; nt++)
            #pragma unroll
            for (int t = 0; t < 4; t++) s[nt][t] = 0.f;
        #pragma unroll
        for (int kf = 0; kf < 8; kf++) {
            #pragma unroll
            for (int nt = 0; nt < 8; nt++) {
                unsigned bb[2];
                bb[0] = __float_as_uint(Ks[(nt*8 + g)*PADK + kf*8 + q    ]);
                bb[1] = __float_as_uint(Ks[(nt*8 + g)*PADK + kf*8 + q + 4]);
                mma_tf32(s[nt], qa[kf], bb);
            }
        }

        // ---- scale + causal mask (diagonal tile only) ----------------------
        #pragma unroll
        for (int nt = 0; nt < 8; nt++) {
            s[nt][0] *= scale; s[nt][1] *= scale;
            s[nt][2] *= scale; s[nt][3] *= scale;
        }
        if (kb == qb) {
            int rl0 = w*16 + g, rl1 = rl0 + 8;
            #pragma unroll
            for (int nt = 0; nt < 8; nt++) {
                int c0 = nt*8 + 2*q, c1 = c0 + 1;
                if (c0 > rl0) s[nt][0] = -1e30f;
                if (c1 > rl0) s[nt][1] = -1e30f;
                if (c0 > rl1) s[nt][2] = -1e30f;
                if (c1 > rl1) s[nt][3] = -1e30f;
            }
        }

        // ---- online softmax ------------------------------------------------
        float tm0 = -1e30f, tm1 = -1e30f;
        #pragma unroll
        for (int nt = 0; nt < 8; nt++) {
            tm0 = fmaxf(tm0, fmaxf(s[nt][0], s[nt][1]));
            tm1 = fmaxf(tm1, fmaxf(s[nt][2], s[nt][3]));
        }
        tm0 = fmaxf(tm0, __shfl_xor_sync(0xffffffffu, tm0, 1));
        tm0 = fmaxf(tm0, __shfl_xor_sync(0xffffffffu, tm0, 2));
        tm1 = fmaxf(tm1, __shfl_xor_sync(0xffffffffu, tm1, 1));
        tm1 = fmaxf(tm1, __shfl_xor_sync(0xffffffffu, tm1, 2));
        float mn0 = fmaxf(m0, tm0), mn1 = fmaxf(m1, tm1);
        float f0 = __expf(m0 - mn0), f1 = __expf(m1 - mn1);
        m0 = mn0; m1 = mn1;
        float sum0 = 0.f, sum1 = 0.f;
        #pragma unroll
        for (int nt = 0; nt < 8; nt++) {
            s[nt][0] = __expf(s[nt][0] - mn0); sum0 += s[nt][0];
            s[nt][1] = __expf(s[nt][1] - mn0); sum0 += s[nt][1];
            s[nt][2] = __expf(s[nt][2] - mn1); sum1 += s[nt][2];
            s[nt][3] = __expf(s[nt][3] - mn1); sum1 += s[nt][3];
        }
        sum0 += __shfl_xor_sync(0xffffffffu, sum0, 1);
        sum0 += __shfl_xor_sync(0xffffffffu, sum0, 2);
        sum1 += __shfl_xor_sync(0xffffffffu, sum1, 1);
        sum1 += __shfl_xor_sync(0xffffffffu, sum1, 2);
        l0 = l0*f0 + sum0;
        l1 = l1*f1 + sum1;
        #pragma unroll
        for (int nt = 0; nt < 8; nt++) {
            o[nt][0] *= f0; o[nt][1] *= f0;
            o[nt][2] *= f1; o[nt][3] *= f1;
        }

        // ---- O += P V : P C-frag -> A-frag via quad shuffles ---------------
        #pragma unroll
        for (int kf = 0; kf < 8; kf++) {
            int src0 = (lane & ~3) | (q >> 1);
            float v00 = __shfl_sync(0xffffffffu, s[kf][0], src0);
            float v01 = __shfl_sync(0xffffffffu, s[kf][1], src0);
            float v10 = __shfl_sync(0xffffffffu, s[kf][2], src0);
            float v11 = __shfl_sync(0xffffffffu, s[kf][3], src0);
            float v20 = __shfl_sync(0xffffffffu, s[kf][0], src0 + 2);
            float v21 = __shfl_sync(0xffffffffu, s[kf][1], src0 + 2);
            float v30 = __shfl_sync(0xffffffffu, s[kf][2], src0 + 2);
            float v31 = __shfl_sync(0xffffffffu, s[kf][3], src0 + 2);
            unsigned pa[4];
            pa[0] = __float_as_uint((q & 1) ? v01 : v00);
            pa[1] = __float_as_uint((q & 1) ? v11 : v10);
            pa[2] = __float_as_uint((q & 1) ? v21 : v20);
            pa[3] = __float_as_uint((q & 1) ? v31 : v30);
            #pragma unroll
            for (int nt = 0; nt < 8; nt++) {
                unsigned vb[2];
                vb[0] = __float_as_uint(Vs[(kf*8 + q    )*PADV + nt*8 + g]);
                vb[1] = __float_as_uint(Vs[(kf*8 + q + 4)*PADV + nt*8 + g]);
                mma_tf32(o[nt], pa, vb);
            }
        }
    }

    // ---- epilogue ----------------------------------------------------------
    float inv0 = 1.0f / l0, inv1 = 1.0f / l1;
    int r0 = qb*64 + w*16 + g, r1 = r0 + 8;
    #pragma unroll
    for (int nt = 0; nt < 8; nt++) {
        float2 v0 = make_float2(o[nt][0]*inv0, o[nt][1]*inv0);
        float2 v1 = make_float2(o[nt][2]*inv1, o[nt][3]*inv1);
        *(float2*)(Y + base + (size_t)r0*(HH*HD) + nt*8 + 2*q) = v0;
        *(float2*)(Y + base + (size_t)r1*(HH*HD) + nt*8 + 2*q) = v1;
    }
    #undef ISSUE_TILE
}

// ---------------- launch ----------------------------------------------------
extern "C" void kernel_launch(void* const* d_in, const int* in_sizes, int n_in,
                              void* d_out, int out_size) {
    const float* x   = (const float*)d_in[0];
    const float* cs  = (const float*)d_in[1];
    const float* sn  = (const float*)d_in[2];
    const float* wq  = (const float*)d_in[3];
    const float* wk  = (const float*)d_in[4];
    const float* wv  = (const float*)d_in[5];
    const float* wo  = (const float*)d_in[6];
    const float* wfc = (const float*)d_in[7];
    const float* wpr = (const float*)d_in[8];
    const float* g1  = (const float*)d_in[9];
    const float* g2  = (const float*)d_in[10];
    float* out = (float*)d_out;

    float *h_, *q_, *k_, *v_, *y_, *x2_, *a_;
    cudaGetSymbolAddress((void**)&h_,  g_h);
    cudaGetSymbolAddress((void**)&q_,  g_q);
    cudaGetSymbolAddress((void**)&k_,  g_k);
    cudaGetSymbolAddress((void**)&v_,  g_v);
    cudaGetSymbolAddress((void**)&y_,  g_y);
    cudaGetSymbolAddress((void**)&x2_, g_x2);
    cudaGetSymbolAddress((void**)&a_,  g_a);

    cudaFuncSetAttribute(attn_tc_k, cudaFuncAttributeMaxDynamicSharedMemorySize,
                         ATTN_SMEM);
    cudaFuncSetAttribute(tfgemm_k<0>, cudaFuncAttributeMaxDynamicSharedMemorySize,
                         GEMM_SMEM);
    cudaFuncSetAttribute(tfgemm_k<1>, cudaFuncAttributeMaxDynamicSharedMemorySize,
                         GEMM_SMEM);
    cudaFuncSetAttribute(tfgemm_k<2>, cudaFuncAttributeMaxDynamicSharedMemorySize,
                         GEMM_SMEM);

    dim3 gemm_qkv(CC/128, MROWS/128, 3);  // (6, 32, 3) fused QKV
    dim3 gemm_cc (CC/128, MROWS/128, 1);  // (6, 32)
    dim3 gemm_ff (FF/128, MROWS/128, 1);  // (24, 32)

    // 1. h = rmsnorm(x, g1)
    rmsnorm_k<<<MROWS, 256>>>(x, g1, h_);
    // 2. q,k,v = h @ w{q,k,v}  (one fused launch)
    tfgemm_k<0><<<gemm_qkv, 256, GEMM_SMEM>>>(h_, wq, wk, wv, q_, k_, v_, nullptr, MROWS, CC, CC);
    // 3. RoPE on q and k (one launch)
    int nrope = BB*TT*HH*D2;
    rope_k<<<dim3((nrope + 255)/256, 2), 256>>>(q_, k_, cs, sn);
    // 4. attention -> y [B,T,H,HD]  (tensor-core flash)
    attn_tc_k<<<dim3(TT/64, BB*HH), 128, ATTN_SMEM>>>(q_, k_, v_, y_);
    // 5. x2 = x + y @ wo
    tfgemm_k<1><<<gemm_cc, 256, GEMM_SMEM>>>(y_, wo, wo, wo, x2_, x2_, x2_, x, MROWS, CC, CC);
    // 6. h = rmsnorm(x2, g2)
    rmsnorm_k<<<MROWS, 256>>>(x2_, g2, h_);
    // 7. a = relu(h @ wfc)^2
    tfgemm_k<2><<<gemm_ff, 256, GEMM_SMEM>>>(h_, wfc, wfc, wfc, a_, a_, a_, nullptr, MROWS, FF, CC);
    // 8. out = x2 + a @ wpr
    tfgemm_k<1><<<gemm_cc, 256, GEMM_SMEM>>>(a_, wpr, wpr, wpr, out, out, out, x2_, MROWS, CC, FF);
}